// round 12
// baseline (speedup 1.0000x reference)
#include <cuda_runtime.h>
#include <cuda_fp16.h>
#include <math.h>
#include <stdint.h>

#define N_NODES 50000
#define NE      800000
#define ETOT    850000
#define DIN     384
#define HID     256
#define HEADS   4
#define CDIM    64
#define EDIM    32
#define NLAYER  2
#define SLOPE   0.2f
#define TOT_H   (N_NODES*HID)

// ---------------- scratch ----------------------------------------------------
__device__ float    g_h   [(size_t)N_NODES*HID];
__device__ __half   g_xlrh[(size_t)N_NODES*512];    // fp16 xl|xr (51 MB)
__device__ __half   g_eph [(size_t)ETOT*HID];       // fp16 ep, CSR order (435 MB)
__device__ int      g_degi[N_NODES];
__device__ int      g_csr_ptr[N_NODES+1];
__device__ int      g_cursor [N_NODES];
__device__ int      g_csr_e [ETOT];
__device__ int      g_csr_s [ETOT];
__device__ __half   g_each [(size_t)ETOT*EDIM];  // ea2 CSR order, fp16 (54 MB)
__device__ float    g_winT [(size_t)HID*DIN];
__device__ float    g_wcatT[(size_t)512*HID];
__device__ float    g_weT  [(size_t)HID*EDIM];   // [n][k] tf32 (natural order)
__device__ float    g_woutT[(size_t)HID*HID];
__device__ double   g_red[2];

// ---------------- helpers ----------------------------------------------------
__device__ __forceinline__ float lrelu(float x){ return x > 0.f ? x : SLOPE*x; }
__device__ __forceinline__ uint32_t f2tf(float f){
    uint32_t u; asm("cvt.rna.tf32.f32 %0, %1;" : "=r"(u) : "f"(f)); return u;
}
__device__ __forceinline__ float tfF(float f){ return __uint_as_float(f2tf(f)); }
__device__ __forceinline__ uint32_t sptr(const void* p){
    return (uint32_t)__cvta_generic_to_shared(p);
}
__device__ __forceinline__ void mma8(float* c, const uint4& a, uint32_t b0, uint32_t b1){
    asm volatile("mma.sync.aligned.m16n8k8.row.col.f32.tf32.tf32.f32 "
        "{%0,%1,%2,%3}, {%4,%5,%6,%7}, {%8,%9}, {%0,%1,%2,%3};"
        : "+f"(c[0]), "+f"(c[1]), "+f"(c[2]), "+f"(c[3])
        : "r"(a.x), "r"(a.y), "r"(a.z), "r"(a.w), "r"(b0), "r"(b1));
}
#define LDSM4(d, addr) \
    asm volatile("ldmatrix.sync.aligned.m8n8.x4.shared.b16 {%0,%1,%2,%3}, [%4];" \
        : "=r"((d).x), "=r"((d).y), "=r"((d).z), "=r"((d).w) : "r"(addr))

// ---------------- setup ------------------------------------------------------
__global__ void k_zero_i(int* p, int n){
    int i = blockIdx.x*blockDim.x + threadIdx.x;
    if (i < n) p[i] = 0;
}
__global__ void k_degc(const int* __restrict__ dst){
    int t = blockIdx.x*blockDim.x + threadIdx.x;
    if (t < NE) atomicAdd(&g_degi[dst[t]], 1);
}

__global__ void k_scan(){
    __shared__ int wsum[32];
    int tid = threadIdx.x, lane = tid & 31, w = tid >> 5;
    int carry = 0;
    if (tid == 0) g_csr_ptr[0] = 0;
    for (int base = 0; base < N_NODES; base += 1024) {
        int i = base + tid;
        int v = (i < N_NODES) ? (g_degi[i] + 1) : 0;
        int x = v;
        #pragma unroll
        for (int off = 1; off < 32; off <<= 1) {
            int nb = __shfl_up_sync(0xffffffffu, x, off);
            if (lane >= off) x += nb;
        }
        if (lane == 31) wsum[w] = x;
        __syncthreads();
        if (w == 0) {
            int y = wsum[lane];
            #pragma unroll
            for (int off = 1; off < 32; off <<= 1) {
                int nb = __shfl_up_sync(0xffffffffu, y, off);
                if (lane >= off) y += nb;
            }
            wsum[lane] = y;
        }
        __syncthreads();
        int add  = (w > 0) ? wsum[w-1] : 0;
        int incl = carry + add + x;
        if (i < N_NODES) { g_csr_ptr[i+1] = incl; g_cursor[i] = incl - v; }
        carry += wsum[31];
        __syncthreads();
    }
}
__global__ void k_scatter(const int* __restrict__ src, const int* __restrict__ dst){
    int t = blockIdx.x*blockDim.x + threadIdx.x;
    if (t >= ETOT) return;
    int s, d;
    if (t < NE) { s = src[t]; d = dst[t]; } else { s = t - NE; d = s; }
    int pos = atomicAdd(&g_cursor[d], 1);
    g_csr_e[pos] = t;
    g_csr_s[pos] = s;
}

// fused: self-loop mean + CSR-ordered fp16 ea tensor (one ea pass)
__global__ __launch_bounds__(256) void k_eafuse(const float* __restrict__ ea){
    int n = (blockIdx.x*256 + threadIdx.x) >> 5;
    int lane = threadIdx.x & 31;
    int p0 = g_csr_ptr[n], p1 = g_csr_ptr[n+1];
    float sum = 0.f; int deg = 0; int selfpos = p0;
    int e_next = g_csr_e[p0];
    for (int pos = p0; pos < p1; pos++) {
        int e = e_next;
        if (pos + 1 < p1) e_next = g_csr_e[pos+1];
        if (e < NE) {
            float v = __ldcs(ea + (size_t)e*EDIM + lane);
            sum += v; deg++;
            g_each[(size_t)pos*EDIM + lane] = __float2half_rn(v);
        } else selfpos = pos;
    }
    float mean = sum / fmaxf((float)deg, 1.f);
    g_each[(size_t)selfpos*EDIM + lane] = __float2half_rn(mean);
}

// ---------------- weight prep ------------------------------------------------
__global__ void k_transpose(const float* __restrict__ in, float* __restrict__ out,
                            int K, int N){
    __shared__ float t[32][33];
    int kb = blockIdx.y*32, nb = blockIdx.x*32;
    int tx = threadIdx.x & 31, ty = threadIdx.x >> 5;
    #pragma unroll
    for (int i = ty; i < 32; i += 8)
        t[i][tx] = in[(size_t)(kb+i)*N + nb + tx];
    __syncthreads();
    #pragma unroll
    for (int i = ty; i < 32; i += 8)
        out[(size_t)(nb+i)*K + kb + tx] = tfF(t[tx][i]);
}
__global__ void k_transcat(const float* __restrict__ wl, const float* __restrict__ wr){
    __shared__ float t[32][33];
    const float* in = blockIdx.z ? wr : wl;
    float* out = g_wcatT + (size_t)blockIdx.z*HID*HID;
    int kb = blockIdx.y*32, nb = blockIdx.x*32;
    int tx = threadIdx.x & 31, ty = threadIdx.x >> 5;
    #pragma unroll
    for (int i = ty; i < 32; i += 8)
        t[i][tx] = in[(size_t)(kb+i)*HID + nb + tx];
    __syncthreads();
    #pragma unroll
    for (int i = ty; i < 32; i += 8)
        out[(size_t)(nb+i)*HID + kb + tx] = tfF(t[tx][i]);
}
// weT[n][k] = we[k][n], tf32; natural order. Also zeroes LN reduction accum.
__global__ void k_weT(const float* __restrict__ we){
    if (blockIdx.x == 0 && threadIdx.x < 2) g_red[threadIdx.x] = 0.0;
    int t = blockIdx.x*blockDim.x + threadIdx.x;
    if (t >= HID*EDIM) return;
    int n = t >> 5, k = t & 31;
    g_weT[t] = tfF(we[(size_t)k*HID + n]);
}

// ---------------- TF32 LDSM GEMM (fp32 or fp16 output) -----------------------
#define APAD 20
__global__ __launch_bounds__(256) void tgemm(
    const float* __restrict__ A, const float* __restrict__ Bt,
    const float* __restrict__ bias, float* __restrict__ C,
    __half* __restrict__ Ch,
    int M, int K, int Nn, int act)
{
    __shared__ float As[2][128*APAD];
    __shared__ float Bs[2][128*APAD];
    const int tid = threadIdx.x, lane = tid & 31, wid = tid >> 5;
    const int wm = (wid & 1)*64, wn = (wid >> 1)*32;
    const int cRow = blockIdx.y*128, cCol = blockIdx.x*128;
    const int r0 = tid >> 2, q0 = tid & 3;

    const int aoff = ((wm + (lane & 15))*APAD + ((lane >> 4) << 2))*4;
    const int boff = ((wn + (lane & 15))*APAD + ((lane >> 4) << 2))*4;

    float acc[4][4][4];
    #pragma unroll
    for (int i = 0; i < 4; i++)
        #pragma unroll
        for (int j = 0; j < 4; j++)
            #pragma unroll
            for (int v = 0; v < 4; v++) acc[i][j][v] = 0.f;

    float4 aR0, aR1, bR0, bR1;
#define LDG_TILE(kt) { \
    int gr0 = cRow + r0, gr1 = gr0 + 64; \
    aR0 = (gr0 < M) ? *(const float4*)(A + (size_t)gr0*K + (kt) + q0*4) : make_float4(0,0,0,0); \
    aR1 = (gr1 < M) ? *(const float4*)(A + (size_t)gr1*K + (kt) + q0*4) : make_float4(0,0,0,0); \
    bR0 = *(const float4*)(Bt + (size_t)(cCol + r0)*K + (kt) + q0*4); \
    bR1 = *(const float4*)(Bt + (size_t)(cCol + r0 + 64)*K + (kt) + q0*4); }
#define STS_TILE(b) { \
    float* pa = &As[b][r0*APAD + q0*4]; \
    *(float4*)pa = make_float4(tfF(aR0.x), tfF(aR0.y), tfF(aR0.z), tfF(aR0.w)); \
    *(float4*)(pa + 64*APAD) = make_float4(tfF(aR1.x), tfF(aR1.y), tfF(aR1.z), tfF(aR1.w)); \
    float* pb = &Bs[b][r0*APAD + q0*4]; \
    *(float4*)pb = bR0; \
    *(float4*)(pb + 64*APAD) = bR1; }
#define COMPUTE(b) { \
    uint32_t ab = sptr(&As[b][0]) + aoff; \
    uint32_t bb = sptr(&Bs[b][0]) + boff; \
    _Pragma("unroll") \
    for (int ks = 0; ks < 2; ks++) { \
        uint4 af0, af1, af2, af3, bf0, bf1; \
        LDSM4(af0, ab + (ks*8)*4); \
        LDSM4(af1, ab + (16*APAD + ks*8)*4); \
        LDSM4(af2, ab + (32*APAD + ks*8)*4); \
        LDSM4(af3, ab + (48*APAD + ks*8)*4); \
        LDSM4(bf0, bb + (ks*8)*4); \
        LDSM4(bf1, bb + (16*APAD + ks*8)*4); \
        mma8(acc[0][0], af0, bf0.x, bf0.z); mma8(acc[0][1], af0, bf0.y, bf0.w); \
        mma8(acc[0][2], af0, bf1.x, bf1.z); mma8(acc[0][3], af0, bf1.y, bf1.w); \
        mma8(acc[1][0], af1, bf0.x, bf0.z); mma8(acc[1][1], af1, bf0.y, bf0.w); \
        mma8(acc[1][2], af1, bf1.x, bf1.z); mma8(acc[1][3], af1, bf1.y, bf1.w); \
        mma8(acc[2][0], af2, bf0.x, bf0.z); mma8(acc[2][1], af2, bf0.y, bf0.w); \
        mma8(acc[2][2], af2, bf1.x, bf1.z); mma8(acc[2][3], af2, bf1.y, bf1.w); \
        mma8(acc[3][0], af3, bf0.x, bf0.z); mma8(acc[3][1], af3, bf0.y, bf0.w); \
        mma8(acc[3][2], af3, bf1.x, bf1.z); mma8(acc[3][3], af3, bf1.y, bf1.w); \
    } }

    LDG_TILE(0);
    STS_TILE(0);
    __syncthreads();
    int buf = 0;
    for (int kt = 16; kt < K; kt += 16) {
        LDG_TILE(kt);
        COMPUTE(buf);
        STS_TILE(buf ^ 1);
        __syncthreads();
        buf ^= 1;
    }
    COMPUTE(buf);

    const int g = lane >> 2, q = lane & 3;
    #pragma unroll
    for (int mf = 0; mf < 4; mf++) {
        int rA = cRow + wm + mf*16 + g;
        #pragma unroll
        for (int nf = 0; nf < 4; nf++) {
            int col = cCol + wn + nf*8 + 2*q;
            float bx = 0.f, by = 0.f;
            if (bias) { float2 bb = *(const float2*)(bias + col); bx = bb.x; by = bb.y; }
            float v0 = acc[mf][nf][0] + bx, v1 = acc[mf][nf][1] + by;
            float v2 = acc[mf][nf][2] + bx, v3 = acc[mf][nf][3] + by;
            if (act == 1) {
                v0 = fmaxf(v0,0.f); v1 = fmaxf(v1,0.f);
                v2 = fmaxf(v2,0.f); v3 = fmaxf(v3,0.f);
            }
            if (Ch) {
                if (rA < M)
                    *(__half2*)(Ch + (size_t)rA*Nn + col) = __floats2half2_rn(v0, v1);
                if (rA+8 < M)
                    *(__half2*)(Ch + (size_t)(rA+8)*Nn + col) = __floats2half2_rn(v2, v3);
            } else {
                if (rA < M)     *(float2*)(C + (size_t)rA*Nn + col)     = make_float2(v0,v1);
                if (rA+8 < M)   *(float2*)(C + (size_t)(rA+8)*Nn + col) = make_float2(v2,v3);
            }
        }
    }
#undef LDG_TILE
#undef STS_TILE
#undef COMPUTE
}

// ---------------- ep GEMM: g_eph[pos][256] = (ea2 @ we) fp16 -----------------
#define EPAD 36
__global__ __launch_bounds__(256) void k_epgemm()
{
    __shared__ float As[128*EPAD];
    __shared__ float Bs[256*EPAD];
    const int tid = threadIdx.x, lane = tid & 31, wid = tid >> 5;
    const int q = lane & 3, g = lane >> 2;
    const int e0 = blockIdx.x * 128;

    #pragma unroll
    for (int i = 0; i < 2; i++) {      // ea tile: fp16 -> fp32 (exact)
        int f = tid + i*256;
        int row = f >> 2, q4 = f & 3;
        int pos = e0 + row;
        uint4 raw = make_uint4(0,0,0,0);
        if (pos < ETOT)
            raw = __ldcs((const uint4*)(g_each + (size_t)pos*EDIM + q4*8));
        float2 f0 = __half22float2(*(__half2*)&raw.x);
        float2 f1 = __half22float2(*(__half2*)&raw.y);
        float2 f2 = __half22float2(*(__half2*)&raw.z);
        float2 f3 = __half22float2(*(__half2*)&raw.w);
        *(float4*)(&As[row*EPAD + q4*8])     = make_float4(f0.x,f0.y,f1.x,f1.y);
        *(float4*)(&As[row*EPAD + q4*8 + 4]) = make_float4(f2.x,f2.y,f3.x,f3.y);
    }
    #pragma unroll
    for (int i = 0; i < 8; i++) {
        int f = tid + i*256;
        int row = f >> 3, q8 = f & 7;
        *(float4*)(&Bs[row*EPAD + q8*4]) =
            *(const float4*)(g_weT + (size_t)row*EDIM + q8*4);
    }
    __syncthreads();

    const int aoff = ((wid*16 + (lane & 15))*EPAD + ((lane >> 4) << 2))*4;
    const int boff = (((lane & 15))*EPAD + ((lane >> 4) << 2))*4;
    const int r0l = wid*16 + g, r1l = r0l + 8;
    const uint32_t ab = sptr(&As[0]) + aoff;
    const uint32_t bb = sptr(&Bs[0]) + boff;
    const int pos0 = e0 + r0l, pos1 = e0 + r1l;

    #pragma unroll
    for (int half = 0; half < 2; half++) {
        float acc[16][4];
        #pragma unroll
        for (int j = 0; j < 16; j++)
            #pragma unroll
            for (int v = 0; v < 4; v++) acc[j][v] = 0.f;
        uint32_t bbh = bb + half*(128*EPAD*4);
        #pragma unroll
        for (int ks = 0; ks < 4; ks++) {
            uint4 a;
            LDSM4(a, ab + (ks*8)*4);
            #pragma unroll
            for (int nt = 0; nt < 8; nt++) {
                uint4 b;
                LDSM4(b, bbh + (nt*16*EPAD + ks*8)*4);
                mma8(acc[nt*2+0], a, b.x, b.z);
                mma8(acc[nt*2+1], a, b.y, b.w);
            }
        }
        #pragma unroll
        for (int j = 0; j < 16; j++) {
            int col = half*128 + (j >> 1)*16 + (j & 1)*8 + 2*q;
            if (pos0 < ETOT)
                *(__half2*)(g_eph + (size_t)pos0*HID + col) =
                    __floats2half2_rn(acc[j][0], acc[j][1]);
            if (pos1 < ETOT)
                *(__half2*)(g_eph + (size_t)pos1*HID + col) =
                    __floats2half2_rn(acc[j][2], acc[j][3]);
        }
    }
}

// ---------------- fused logits + softmax + aggregation (warp per node) -------
__global__ __launch_bounds__(256) void k_nodefuse(const float* __restrict__ attL,
                                                  const float* __restrict__ bconv)
{
    const int n    = (blockIdx.x*256 + threadIdx.x) >> 5;
    const int lane = threadIdx.x & 31;
    const int p0 = g_csr_ptr[n], p1 = g_csr_ptr[n+1];

    // xr row = own node's lin_r projection (loaded once)
    float xr[8], at[8];
    {
        uint4 raw = *(const uint4*)(g_xlrh + (size_t)n*512 + 256 + lane*8);
        float2 f0 = __half22float2(*(__half2*)&raw.x);
        float2 f1 = __half22float2(*(__half2*)&raw.y);
        float2 f2 = __half22float2(*(__half2*)&raw.z);
        float2 f3 = __half22float2(*(__half2*)&raw.w);
        xr[0]=f0.x; xr[1]=f0.y; xr[2]=f1.x; xr[3]=f1.y;
        xr[4]=f2.x; xr[5]=f2.y; xr[6]=f3.x; xr[7]=f3.y;
        float4 a0 = *(const float4*)(attL + lane*8);
        float4 a1 = *(const float4*)(attL + lane*8 + 4);
        at[0]=a0.x; at[1]=a0.y; at[2]=a0.z; at[3]=a0.w;
        at[4]=a1.x; at[5]=a1.y; at[6]=a1.z; at[7]=a1.w;
    }

    float acc[8];
    #pragma unroll
    for (int j = 0; j < 8; j++) acc[j] = 0.f;
    float dsum = 0.f;

    int   s_nx   = g_csr_s[p0];
    uint4 xl_nx  = *(const uint4*)(g_xlrh + (size_t)s_nx*512 + lane*8);
    uint4 ep_nx  = __ldcs((const uint4*)(g_eph + (size_t)p0*HID + lane*8));

    for (int pos = p0; pos < p1; pos++) {
        uint4 xlr = xl_nx, epr = ep_nx;
        if (pos + 1 < p1) {
            int s2 = g_csr_s[pos+1];
            xl_nx = *(const uint4*)(g_xlrh + (size_t)s2*512 + lane*8);
            ep_nx = __ldcs((const uint4*)(g_eph + (size_t)(pos+1)*HID + lane*8));
        }
        float xl[8], ep[8];
        {
            float2 f0 = __half22float2(*(__half2*)&xlr.x);
            float2 f1 = __half22float2(*(__half2*)&xlr.y);
            float2 f2 = __half22float2(*(__half2*)&xlr.z);
            float2 f3 = __half22float2(*(__half2*)&xlr.w);
            xl[0]=f0.x; xl[1]=f0.y; xl[2]=f1.x; xl[3]=f1.y;
            xl[4]=f2.x; xl[5]=f2.y; xl[6]=f3.x; xl[7]=f3.y;
            float2 g0 = __half22float2(*(__half2*)&epr.x);
            float2 g1 = __half22float2(*(__half2*)&epr.y);
            float2 g2 = __half22float2(*(__half2*)&epr.z);
            float2 g3 = __half22float2(*(__half2*)&epr.w);
            ep[0]=g0.x; ep[1]=g0.y; ep[2]=g1.x; ep[3]=g1.y;
            ep[4]=g2.x; ep[5]=g2.y; ep[6]=g3.x; ep[7]=g3.y;
        }
        float p = 0.f;
        #pragma unroll
        for (int j = 0; j < 8; j++)
            p += lrelu(xl[j] + xr[j] + ep[j]) * at[j];
        p += __shfl_xor_sync(0xffffffffu, p, 1);
        p += __shfl_xor_sync(0xffffffffu, p, 2);
        p += __shfl_xor_sync(0xffffffffu, p, 4);
        float ex = __expf(p);
        dsum += ex;
        #pragma unroll
        for (int j = 0; j < 8; j++) acc[j] += ex * xl[j];
    }
    const float ih = 1.f / (dsum + 1e-16f);

    float* ph = g_h + (size_t)n*HID + lane*8;
    float4 h0 = __ldcs((const float4*)ph);
    float4 h1 = __ldcs((const float4*)(ph+4));
    float4 b0 = *(const float4*)(bconv + lane*8);
    float4 b1 = *(const float4*)(bconv + lane*8 + 4);
    float hv[8] = {h0.x,h0.y,h0.z,h0.w,h1.x,h1.y,h1.z,h1.w};
    float bv[8] = {b0.x,b0.y,b0.z,b0.w,b1.x,b1.y,b1.z,b1.w};
    float s_ = 0.f, q_ = 0.f;
    float out8[8];
    #pragma unroll
    for (int j = 0; j < 8; j++) {
        float v  = acc[j]*ih + bv[j];
        float el = v > 0.f ? v : (__expf(v) - 1.f);
        float t  = hv[j] + el;
        out8[j] = t; s_ += t; q_ += t*t;
    }
    __stcs((float4*)ph,     make_float4(out8[0],out8[1],out8[2],out8[3]));
    __stcs((float4*)(ph+4), make_float4(out8[4],out8[5],out8[6],out8[7]));
    #pragma unroll
    for (int off = 16; off; off >>= 1) {
        s_ += __shfl_down_sync(0xffffffffu, s_, off);
        q_ += __shfl_down_sync(0xffffffffu, q_, off);
    }
    __shared__ float ss[8], sq[8];
    int w = threadIdx.x >> 5;
    if (lane == 0) { ss[w] = s_; sq[w] = q_; }
    __syncthreads();
    if (threadIdx.x == 0) {
        float S = 0.f, Q = 0.f;
        #pragma unroll
        for (int i = 0; i < 8; i++) { S += ss[i]; Q += sq[i]; }
        atomicAdd(&g_red[0], (double)S);
        atomicAdd(&g_red[1], (double)Q);
    }
}

__global__ void k_norm(const float* __restrict__ lnw, const float* __restrict__ lnb){
    int idx = blockIdx.x*blockDim.x + threadIdx.x;
    if (idx >= TOT_H) return;
    int c = idx & (HID-1);
    double M  = (double)TOT_H;
    double mu = g_red[0] / M;
    double var = g_red[1] / M - mu*mu;
    if (var < 0.0) var = 0.0;
    float rs = (float)(1.0 / (sqrt(var) + 1e-5));
    float v = __ldcs(&g_h[idx]);
    __stcs(&g_h[idx], (v - (float)mu) * rs * lnw[c] + lnb[c]);
}

// ---------------- launcher ---------------------------------------------------
extern "C" void kernel_launch(void* const* d_in, const int* in_sizes, int n_in,
                              void* d_out, int out_size)
{
    const float* x     = (const float*)d_in[0];
    const int*   ei    = (const int*)  d_in[1];
    const float* ea    = (const float*)d_in[2];
    const float* w_in  = (const float*)d_in[3];
    const float* b_in  = (const float*)d_in[4];
    const float* wl    = (const float*)d_in[5];
    const float* wr    = (const float*)d_in[6];
    const float* we    = (const float*)d_in[7];
    const float* att   = (const float*)d_in[8];
    const float* bconv = (const float*)d_in[9];
    const float* lnw   = (const float*)d_in[10];
    const float* lnb   = (const float*)d_in[11];
    const float* wout  = (const float*)d_in[12];
    const float* bout  = (const float*)d_in[13];
    float* out = (float*)d_out;
    const int* srcA = ei;
    const int* dstA = ei + NE;

    float *p_h, *p_winT, *p_wcatT, *p_woutT;
    __half* p_xlrh;
    int* p_degi;
    cudaGetSymbolAddress((void**)&p_h,     g_h);
    cudaGetSymbolAddress((void**)&p_xlrh,  g_xlrh);
    cudaGetSymbolAddress((void**)&p_degi,  g_degi);
    cudaGetSymbolAddress((void**)&p_winT,  g_winT);
    cudaGetSymbolAddress((void**)&p_wcatT, g_wcatT);
    cudaGetSymbolAddress((void**)&p_woutT, g_woutT);

    dim3 gIn (HID/128, (N_NODES + 127)/128);
    dim3 gXlr(512/128, (N_NODES + 127)/128);

    // launch index 3 = the big N=512 tgemm (profiled slot)
    k_transpose<<<dim3(HID/32, DIN/32), 256>>>(w_in, p_winT, DIN, HID);
    tgemm<<<gIn, 256>>>(x, p_winT, b_in, p_h, nullptr, N_NODES, DIN, HID, 1);
    k_transcat<<<dim3(8, 8, 2), 256>>>(wl, wr);
    tgemm<<<gXlr, 256>>>(p_h, p_wcatT, nullptr, nullptr, p_xlrh, N_NODES, HID, 512, 0);

    // edge preprocessing + CSR
    k_zero_i<<<(N_NODES + 511)/512, 512>>>(p_degi, N_NODES);
    k_degc<<<(NE + 255)/256, 256>>>(dstA);
    k_scan<<<1, 1024>>>();
    k_scatter<<<(ETOT + 255)/256, 256>>>(srcA, dstA);
    k_eafuse<<<N_NODES/8, 256>>>(ea);
    k_transpose<<<dim3(HID/32, HID/32), 256>>>(wout, p_woutT, HID, HID);

    for (int l = 0; l < NLAYER; l++) {
        if (l > 0) {
            k_transcat<<<dim3(8, 8, 2), 256>>>(wl + (size_t)l*HID*HID,
                                               wr + (size_t)l*HID*HID);
            tgemm<<<gXlr, 256>>>(p_h, p_wcatT, nullptr, nullptr, p_xlrh,
                                 N_NODES, HID, 512, 0);
        }
        k_weT<<<(HID*EDIM + 255)/256, 256>>>(we + (size_t)l*EDIM*HID);
        k_epgemm<<<(ETOT + 127)/128, 256>>>();
        k_nodefuse<<<N_NODES/8, 256>>>(att + (size_t)l*HEADS*CDIM,
                                       bconv + (size_t)l*HID);
        k_norm<<<TOT_H/256, 256>>>(lnw + (size_t)l*HID, lnb + (size_t)l*HID);
    }
    tgemm<<<gIn, 256>>>(p_h, p_woutT, bout, out, nullptr, N_NODES, HID, HID, 0);
}

// round 13
// speedup vs baseline: 1.0594x; 1.0594x over previous
#include <cuda_runtime.h>
#include <cuda_fp16.h>
#include <math.h>
#include <stdint.h>

#define N_NODES 50000
#define NE      800000
#define ETOT    850000
#define DIN     384
#define HID     256
#define HEADS   4
#define CDIM    64
#define EDIM    32
#define NLAYER  2
#define SLOPE   0.2f
#define TOT_H   (N_NODES*HID)

// ---------------- scratch ----------------------------------------------------
__device__ float    g_h   [(size_t)N_NODES*HID];
__device__ __half   g_xlrh[(size_t)N_NODES*512];    // fp16 xl|xr (51 MB)
__device__ int      g_degi[N_NODES];
__device__ float    g_logits[(size_t)ETOT*HEADS];   // CSR order; later holds exp(logit)
__device__ int      g_csr_ptr[N_NODES+1];
__device__ int      g_cursor [N_NODES];
__device__ int      g_csr_e [ETOT];
__device__ int      g_csr_s [ETOT];
__device__ int      g_csr_d [ETOT];
__device__ __half   g_each [(size_t)ETOT*EDIM];  // ea2 CSR order, fp16 (54 MB)
__device__ float    g_winT [(size_t)HID*DIN];
__device__ float    g_wcatT[(size_t)512*HID];
__device__ float    g_weT  [(size_t)HID*EDIM];   // [n_frag][k] tf32, col-permuted
__device__ float    g_woutT[(size_t)HID*HID];
__device__ double   g_red[2];

// ---------------- helpers ----------------------------------------------------
__device__ __forceinline__ float lrelu(float x){ return x > 0.f ? x : SLOPE*x; }
__device__ __forceinline__ float sel4(float4 v, int h){
    return h==0 ? v.x : (h==1 ? v.y : (h==2 ? v.z : v.w));
}
__device__ __forceinline__ uint32_t f2tf(float f){
    uint32_t u; asm("cvt.rna.tf32.f32 %0, %1;" : "=r"(u) : "f"(f)); return u;
}
__device__ __forceinline__ float tfF(float f){ return __uint_as_float(f2tf(f)); }
__device__ __forceinline__ uint32_t sptr(const void* p){
    return (uint32_t)__cvta_generic_to_shared(p);
}
__device__ __forceinline__ void mma8(float* c, const uint4& a, uint32_t b0, uint32_t b1){
    asm volatile("mma.sync.aligned.m16n8k8.row.col.f32.tf32.tf32.f32 "
        "{%0,%1,%2,%3}, {%4,%5,%6,%7}, {%8,%9}, {%0,%1,%2,%3};"
        : "+f"(c[0]), "+f"(c[1]), "+f"(c[2]), "+f"(c[3])
        : "r"(a.x), "r"(a.y), "r"(a.z), "r"(a.w), "r"(b0), "r"(b1));
}
#define LDSM4(d, addr) \
    asm volatile("ldmatrix.sync.aligned.m8n8.x4.shared.b16 {%0,%1,%2,%3}, [%4];" \
        : "=r"((d).x), "=r"((d).y), "=r"((d).z), "=r"((d).w) : "r"(addr))

// ---------------- setup ------------------------------------------------------
__global__ void k_zero_i(int* p, int n){
    int i = blockIdx.x*blockDim.x + threadIdx.x;
    if (i < n) p[i] = 0;
}
__global__ void k_degc(const int* __restrict__ dst){
    int t = blockIdx.x*blockDim.x + threadIdx.x;
    if (t < NE) atomicAdd(&g_degi[dst[t]], 1);
}

__global__ void k_scan(){
    __shared__ int wsum[32];
    int tid = threadIdx.x, lane = tid & 31, w = tid >> 5;
    int carry = 0;
    if (tid == 0) g_csr_ptr[0] = 0;
    for (int base = 0; base < N_NODES; base += 1024) {
        int i = base + tid;
        int v = (i < N_NODES) ? (g_degi[i] + 1) : 0;
        int x = v;
        #pragma unroll
        for (int off = 1; off < 32; off <<= 1) {
            int nb = __shfl_up_sync(0xffffffffu, x, off);
            if (lane >= off) x += nb;
        }
        if (lane == 31) wsum[w] = x;
        __syncthreads();
        if (w == 0) {
            int y = wsum[lane];
            #pragma unroll
            for (int off = 1; off < 32; off <<= 1) {
                int nb = __shfl_up_sync(0xffffffffu, y, off);
                if (lane >= off) y += nb;
            }
            wsum[lane] = y;
        }
        __syncthreads();
        int add  = (w > 0) ? wsum[w-1] : 0;
        int incl = carry + add + x;
        if (i < N_NODES) { g_csr_ptr[i+1] = incl; g_cursor[i] = incl - v; }
        carry += wsum[31];
        __syncthreads();
    }
}
__global__ void k_scatter(const int* __restrict__ src, const int* __restrict__ dst){
    int t = blockIdx.x*blockDim.x + threadIdx.x;
    if (t >= ETOT) return;
    int s, d;
    if (t < NE) { s = src[t]; d = dst[t]; } else { s = t - NE; d = s; }
    int pos = atomicAdd(&g_cursor[d], 1);
    g_csr_e[pos] = t;
    g_csr_s[pos] = s;
    g_csr_d[pos] = d;
}

// fused: self-loop mean + CSR-ordered fp16 ea tensor (one ea pass, prefetched)
__global__ __launch_bounds__(256) void k_eafuse(const float* __restrict__ ea){
    int n = (blockIdx.x*256 + threadIdx.x) >> 5;
    int lane = threadIdx.x & 31;
    int p0 = g_csr_ptr[n], p1 = g_csr_ptr[n+1];
    float sum = 0.f; int deg = 0; int selfpos = p0;
    int e_next = g_csr_e[p0];
    for (int pos = p0; pos < p1; pos++) {
        int e = e_next;
        if (pos + 1 < p1) e_next = g_csr_e[pos+1];
        if (e < NE) {
            float v = __ldcs(ea + (size_t)e*EDIM + lane);
            sum += v; deg++;
            g_each[(size_t)pos*EDIM + lane] = __float2half_rn(v);
        } else selfpos = pos;
    }
    float mean = sum / fmaxf((float)deg, 1.f);
    g_each[(size_t)selfpos*EDIM + lane] = __float2half_rn(mean);
}

// ---------------- weight prep ------------------------------------------------
__global__ void k_transpose(const float* __restrict__ in, float* __restrict__ out,
                            int K, int N){
    __shared__ float t[32][33];
    int kb = blockIdx.y*32, nb = blockIdx.x*32;
    int tx = threadIdx.x & 31, ty = threadIdx.x >> 5;
    #pragma unroll
    for (int i = ty; i < 32; i += 8)
        t[i][tx] = in[(size_t)(kb+i)*N + nb + tx];
    __syncthreads();
    #pragma unroll
    for (int i = ty; i < 32; i += 8)
        out[(size_t)(nb+i)*K + kb + tx] = tfF(t[tx][i]);
}
__global__ void k_transcat(const float* __restrict__ wl, const float* __restrict__ wr){
    __shared__ float t[32][33];
    const float* in = blockIdx.z ? wr : wl;
    float* out = g_wcatT + (size_t)blockIdx.z*HID*HID;
    int kb = blockIdx.y*32, nb = blockIdx.x*32;
    int tx = threadIdx.x & 31, ty = threadIdx.x >> 5;
    #pragma unroll
    for (int i = ty; i < 32; i += 8)
        t[i][tx] = in[(size_t)(kb+i)*HID + nb + tx];
    __syncthreads();
    #pragma unroll
    for (int i = ty; i < 32; i += 8)
        out[(size_t)(nb+i)*HID + kb + tx] = tfF(t[tx][i]);
}
// fragment (j=2t+p, q, pair) -> actual col = half*128 + hh*64 + t*16 + q*4 + p*2 + pair
// also zeroes the LN reduction accumulators
__global__ void k_weT(const float* __restrict__ we){
    if (blockIdx.x == 0 && threadIdx.x < 2) g_red[threadIdx.x] = 0.0;
    int t = blockIdx.x*blockDim.x + threadIdx.x;
    if (t >= HID*EDIM) return;
    int n_f = t >> 5, k = t & 31;
    int half = n_f >> 7, rem = n_f & 127;
    int hh  = rem >> 6;
    int jm  = (rem >> 3) & 7;
    int low = rem & 7, qq = low >> 1, pair = low & 1;
    int tt = jm >> 1, p = jm & 1;
    int a = half*128 + hh*64 + tt*16 + qq*4 + p*2 + pair;
    g_weT[t] = tfF(we[(size_t)k*HID + a]);
}

// ---------------- TF32 LDSM GEMM (fp32 or fp16 output) -----------------------
#define APAD 20
__global__ __launch_bounds__(256) void tgemm(
    const float* __restrict__ A, const float* __restrict__ Bt,
    const float* __restrict__ bias, float* __restrict__ C,
    __half* __restrict__ Ch,
    int M, int K, int Nn, int act)
{
    __shared__ float As[2][128*APAD];
    __shared__ float Bs[2][128*APAD];
    const int tid = threadIdx.x, lane = tid & 31, wid = tid >> 5;
    const int wm = (wid & 1)*64, wn = (wid >> 1)*32;
    const int cRow = blockIdx.y*128, cCol = blockIdx.x*128;
    const int r0 = tid >> 2, q0 = tid & 3;

    const int aoff = ((wm + (lane & 15))*APAD + ((lane >> 4) << 2))*4;
    const int boff = ((wn + (lane & 15))*APAD + ((lane >> 4) << 2))*4;

    float acc[4][4][4];
    #pragma unroll
    for (int i = 0; i < 4; i++)
        #pragma unroll
        for (int j = 0; j < 4; j++)
            #pragma unroll
            for (int v = 0; v < 4; v++) acc[i][j][v] = 0.f;

    float4 aR0, aR1, bR0, bR1;
#define LDG_TILE(kt) { \
    int gr0 = cRow + r0, gr1 = gr0 + 64; \
    aR0 = (gr0 < M) ? *(const float4*)(A + (size_t)gr0*K + (kt) + q0*4) : make_float4(0,0,0,0); \
    aR1 = (gr1 < M) ? *(const float4*)(A + (size_t)gr1*K + (kt) + q0*4) : make_float4(0,0,0,0); \
    bR0 = *(const float4*)(Bt + (size_t)(cCol + r0)*K + (kt) + q0*4); \
    bR1 = *(const float4*)(Bt + (size_t)(cCol + r0 + 64)*K + (kt) + q0*4); }
#define STS_TILE(b) { \
    float* pa = &As[b][r0*APAD + q0*4]; \
    *(float4*)pa = make_float4(tfF(aR0.x), tfF(aR0.y), tfF(aR0.z), tfF(aR0.w)); \
    *(float4*)(pa + 64*APAD) = make_float4(tfF(aR1.x), tfF(aR1.y), tfF(aR1.z), tfF(aR1.w)); \
    float* pb = &Bs[b][r0*APAD + q0*4]; \
    *(float4*)pb = bR0; \
    *(float4*)(pb + 64*APAD) = bR1; }
#define COMPUTE(b) { \
    uint32_t ab = sptr(&As[b][0]) + aoff; \
    uint32_t bb = sptr(&Bs[b][0]) + boff; \
    _Pragma("unroll") \
    for (int ks = 0; ks < 2; ks++) { \
        uint4 af0, af1, af2, af3, bf0, bf1; \
        LDSM4(af0, ab + (ks*8)*4); \
        LDSM4(af1, ab + (16*APAD + ks*8)*4); \
        LDSM4(af2, ab + (32*APAD + ks*8)*4); \
        LDSM4(af3, ab + (48*APAD + ks*8)*4); \
        LDSM4(bf0, bb + (ks*8)*4); \
        LDSM4(bf1, bb + (16*APAD + ks*8)*4); \
        mma8(acc[0][0], af0, bf0.x, bf0.z); mma8(acc[0][1], af0, bf0.y, bf0.w); \
        mma8(acc[0][2], af0, bf1.x, bf1.z); mma8(acc[0][3], af0, bf1.y, bf1.w); \
        mma8(acc[1][0], af1, bf0.x, bf0.z); mma8(acc[1][1], af1, bf0.y, bf0.w); \
        mma8(acc[1][2], af1, bf1.x, bf1.z); mma8(acc[1][3], af1, bf1.y, bf1.w); \
        mma8(acc[2][0], af2, bf0.x, bf0.z); mma8(acc[2][1], af2, bf0.y, bf0.w); \
        mma8(acc[2][2], af2, bf1.x, bf1.z); mma8(acc[2][3], af2, bf1.y, bf1.w); \
        mma8(acc[3][0], af3, bf0.x, bf0.z); mma8(acc[3][1], af3, bf0.y, bf0.w); \
        mma8(acc[3][2], af3, bf1.x, bf1.z); mma8(acc[3][3], af3, bf1.y, bf1.w); \
    } }

    LDG_TILE(0);
    STS_TILE(0);
    __syncthreads();
    int buf = 0;
    for (int kt = 16; kt < K; kt += 16) {
        LDG_TILE(kt);
        COMPUTE(buf);
        STS_TILE(buf ^ 1);
        __syncthreads();
        buf ^= 1;
    }
    COMPUTE(buf);

    const int g = lane >> 2, q = lane & 3;
    #pragma unroll
    for (int mf = 0; mf < 4; mf++) {
        int rA = cRow + wm + mf*16 + g;
        #pragma unroll
        for (int nf = 0; nf < 4; nf++) {
            int col = cCol + wn + nf*8 + 2*q;
            float bx = 0.f, by = 0.f;
            if (bias) { float2 bb = *(const float2*)(bias + col); bx = bb.x; by = bb.y; }
            float v0 = acc[mf][nf][0] + bx, v1 = acc[mf][nf][1] + by;
            float v2 = acc[mf][nf][2] + bx, v3 = acc[mf][nf][3] + by;
            if (act == 1) {
                v0 = fmaxf(v0,0.f); v1 = fmaxf(v1,0.f);
                v2 = fmaxf(v2,0.f); v3 = fmaxf(v3,0.f);
            }
            if (Ch) {
                if (rA < M)
                    *(__half2*)(Ch + (size_t)rA*Nn + col) = __floats2half2_rn(v0, v1);
                if (rA+8 < M)
                    *(__half2*)(Ch + (size_t)(rA+8)*Nn + col) = __floats2half2_rn(v2, v3);
            } else {
                if (rA < M)     *(float2*)(C + (size_t)rA*Nn + col)     = make_float2(v0,v1);
                if (rA+8 < M)   *(float2*)(C + (size_t)(rA+8)*Nn + col) = make_float2(v2,v3);
            }
        }
    }
#undef LDG_TILE
#undef STS_TILE
#undef COMPUTE
}

// ---------------- fused ep-GEMM + logits (fp16 ea + fp16 xlr) ----------------
#define EPAD 36
__global__ __launch_bounds__(256) void k_eplogits(const float* __restrict__ attL)
{
    __shared__ float As[128*EPAD];
    __shared__ float Bs[256*EPAD];
    __shared__ int s_src[128], s_dst[128];
    const int tid = threadIdx.x, lane = tid & 31, wid = tid >> 5;
    const int q = lane & 3, g = lane >> 2;
    const int e0 = blockIdx.x * 128;

    for (int i = tid; i < 128; i += 256) {
        int pos = e0 + i, s = 0, d = 0;
        if (pos < ETOT) { s = g_csr_s[pos]; d = g_csr_d[pos]; }
        s_src[i] = s; s_dst[i] = d;
    }
    #pragma unroll
    for (int i = 0; i < 2; i++) {      // ea tile: fp16 -> fp32 (exact)
        int f = tid + i*256;
        int row = f >> 2, q4 = f & 3;
        int pos = e0 + row;
        uint4 raw = make_uint4(0,0,0,0);
        if (pos < ETOT)
            raw = __ldcs((const uint4*)(g_each + (size_t)pos*EDIM + q4*8));
        float2 f0 = __half22float2(*(__half2*)&raw.x);
        float2 f1 = __half22float2(*(__half2*)&raw.y);
        float2 f2 = __half22float2(*(__half2*)&raw.z);
        float2 f3 = __half22float2(*(__half2*)&raw.w);
        *(float4*)(&As[row*EPAD + q4*8])     = make_float4(f0.x,f0.y,f1.x,f1.y);
        *(float4*)(&As[row*EPAD + q4*8 + 4]) = make_float4(f2.x,f2.y,f3.x,f3.y);
    }
    #pragma unroll
    for (int i = 0; i < 8; i++) {
        int f = tid + i*256;
        int row = f >> 3, q8 = f & 7;
        *(float4*)(&Bs[row*EPAD + q8*4]) =
            *(const float4*)(g_weT + (size_t)row*EDIM + q8*4);
    }
    __syncthreads();

    const int aoff = ((wid*16 + (lane & 15))*EPAD + ((lane >> 4) << 2))*4;
    const int boff = (((lane & 15))*EPAD + ((lane >> 4) << 2))*4;
    const int r0l = wid*16 + g, r1l = r0l + 8;
    const int s0 = s_src[r0l], d0 = s_dst[r0l];
    const int s1 = s_src[r1l], d1 = s_dst[r1l];
    const uint32_t ab = sptr(&As[0]) + aoff;
    const uint32_t bb = sptr(&Bs[0]) + boff;

    #pragma unroll
    for (int half = 0; half < 2; half++) {
        float acc[16][4];
        #pragma unroll
        for (int j = 0; j < 16; j++)
            #pragma unroll
            for (int v = 0; v < 4; v++) acc[j][v] = 0.f;
        uint32_t bbh = bb + half*(128*EPAD*4);
        #pragma unroll
        for (int ks = 0; ks < 4; ks++) {
            uint4 a;
            LDSM4(a, ab + (ks*8)*4);
            #pragma unroll
            for (int nt = 0; nt < 8; nt++) {
                uint4 b;
                LDSM4(b, bbh + (nt*16*EPAD + ks*8)*4);
                mma8(acc[nt*2+0], a, b.x, b.z);
                mma8(acc[nt*2+1], a, b.y, b.w);
            }
        }
        float p0h0 = 0.f, p0h1 = 0.f, p1h0 = 0.f, p1h1 = 0.f;
        #pragma unroll
        for (int hh = 0; hh < 2; hh++) {
            #pragma unroll
            for (int t = 0; t < 4; t++) {
                int cb = half*128 + hh*64 + t*16 + q*4;
                float4 at = *(const float4*)(attL + cb);
                uint2 ra0 = *(const uint2*)(g_xlrh + (size_t)s0*512 + cb);
                uint2 rb0 = *(const uint2*)(g_xlrh + (size_t)d0*512 + 256 + cb);
                uint2 ra1 = *(const uint2*)(g_xlrh + (size_t)s1*512 + cb);
                uint2 rb1 = *(const uint2*)(g_xlrh + (size_t)d1*512 + 256 + cb);
                float2 a0l = __half22float2(*(__half2*)&ra0.x);
                float2 a0h = __half22float2(*(__half2*)&ra0.y);
                float2 b0l = __half22float2(*(__half2*)&rb0.x);
                float2 b0h = __half22float2(*(__half2*)&rb0.y);
                float2 a1l = __half22float2(*(__half2*)&ra1.x);
                float2 a1h = __half22float2(*(__half2*)&ra1.y);
                float2 b1l = __half22float2(*(__half2*)&rb1.x);
                float2 b1h = __half22float2(*(__half2*)&rb1.y);
                int ja = hh*8 + 2*t;
                float c0 = lrelu(acc[ja][0]   + a0l.x + b0l.x)*at.x
                         + lrelu(acc[ja][1]   + a0l.y + b0l.y)*at.y
                         + lrelu(acc[ja+1][0] + a0h.x + b0h.x)*at.z
                         + lrelu(acc[ja+1][1] + a0h.y + b0h.y)*at.w;
                float c1 = lrelu(acc[ja][2]   + a1l.x + b1l.x)*at.x
                         + lrelu(acc[ja][3]   + a1l.y + b1l.y)*at.y
                         + lrelu(acc[ja+1][2] + a1h.x + b1h.x)*at.z
                         + lrelu(acc[ja+1][3] + a1h.y + b1h.y)*at.w;
                if (hh == 0) { p0h0 += c0; p1h0 += c1; }
                else         { p0h1 += c0; p1h1 += c1; }
            }
        }
        #pragma unroll
        for (int off = 1; off <= 2; off <<= 1) {
            p0h0 += __shfl_xor_sync(0xffffffffu, p0h0, off);
            p0h1 += __shfl_xor_sync(0xffffffffu, p0h1, off);
            p1h0 += __shfl_xor_sync(0xffffffffu, p1h0, off);
            p1h1 += __shfl_xor_sync(0xffffffffu, p1h1, off);
        }
        if (q == 0) {
            if (e0 + r0l < ETOT) {
                g_logits[(size_t)(e0 + r0l)*HEADS + half*2 + 0] = p0h0;
                g_logits[(size_t)(e0 + r0l)*HEADS + half*2 + 1] = p0h1;
            }
            if (e0 + r1l < ETOT) {
                g_logits[(size_t)(e0 + r1l)*HEADS + half*2 + 0] = p1h0;
                g_logits[(size_t)(e0 + r1l)*HEADS + half*2 + 1] = p1h1;
            }
        }
    }
}

// ---------------- node aggregation (exp-once softmax, 2-deep pipeline) -------
__global__ __launch_bounds__(256) void k_nodeagg(const float* __restrict__ bconv){
    const int n    = (blockIdx.x*256 + threadIdx.x) >> 5;
    const int lane = threadIdx.x & 31;
    const int p0 = g_csr_ptr[n], p1 = g_csr_ptr[n+1];
    // phase B: ex = exp(logit) once per edge (strided), store back, accum denom
    float4 sm = make_float4(0,0,0,0);
    for (int idx = p0 + lane; idx < p1; idx += 32) {
        float4 lg = *(const float4*)(g_logits + (size_t)idx*HEADS);
        float4 ex = make_float4(__expf(lg.x), __expf(lg.y), __expf(lg.z), __expf(lg.w));
        *(float4*)(g_logits + (size_t)idx*HEADS) = ex;
        sm.x += ex.x; sm.y += ex.y; sm.z += ex.z; sm.w += ex.w;
    }
    #pragma unroll
    for (int off = 16; off; off >>= 1) {
        sm.x += __shfl_xor_sync(0xffffffffu, sm.x, off);
        sm.y += __shfl_xor_sync(0xffffffffu, sm.y, off);
        sm.z += __shfl_xor_sync(0xffffffffu, sm.z, off);
        sm.w += __shfl_xor_sync(0xffffffffu, sm.w, off);
    }
    __syncwarp();
    const int head = lane >> 3;
    const float ih = 1.f / (sel4(sm, head) + 1e-16f);
    // phase C: 2-deep pipelined weighted aggregation
    float acc[8];
    #pragma unroll
    for (int j = 0; j < 8; j++) acc[j] = 0.f;
    const int cnt = p1 - p0;          // >= 1 (self loop)
    float4 ex0, ex1;
    uint4  rw0, rw1;
    {
        int s0 = g_csr_s[p0];
        ex0 = *(const float4*)(g_logits + (size_t)p0*HEADS);
        rw0 = *(const uint4*)(g_xlrh + (size_t)s0*512 + lane*8);
    }
    if (cnt > 1) {
        int s1 = g_csr_s[p0+1];
        ex1 = *(const float4*)(g_logits + (size_t)(p0+1)*HEADS);
        rw1 = *(const uint4*)(g_xlrh + (size_t)s1*512 + lane*8);
    }
    for (int i = 0; i < cnt; i++) {
        float4 ex = (i & 1) ? ex1 : ex0;
        uint4  raw = (i & 1) ? rw1 : rw0;
        if (i + 2 < cnt) {
            int s2 = g_csr_s[p0 + i + 2];
            if (i & 1) {
                ex1 = *(const float4*)(g_logits + (size_t)(p0+i+2)*HEADS);
                rw1 = *(const uint4*)(g_xlrh + (size_t)s2*512 + lane*8);
            } else {
                ex0 = *(const float4*)(g_logits + (size_t)(p0+i+2)*HEADS);
                rw0 = *(const uint4*)(g_xlrh + (size_t)s2*512 + lane*8);
            }
        }
        float w = sel4(ex, head) * ih;
        float2 f0 = __half22float2(*(__half2*)&raw.x);
        float2 f1 = __half22float2(*(__half2*)&raw.y);
        float2 f2 = __half22float2(*(__half2*)&raw.z);
        float2 f3 = __half22float2(*(__half2*)&raw.w);
        acc[0] += w*f0.x; acc[1] += w*f0.y; acc[2] += w*f1.x; acc[3] += w*f1.y;
        acc[4] += w*f2.x; acc[5] += w*f2.y; acc[6] += w*f3.x; acc[7] += w*f3.y;
    }
    float* ph = g_h + (size_t)n*HID + lane*8;
    float4 h0 = __ldcs((const float4*)ph);
    float4 h1 = __ldcs((const float4*)(ph+4));
    float4 b0 = *(const float4*)(bconv + lane*8);
    float4 b1 = *(const float4*)(bconv + lane*8 + 4);
    float hv[8] = {h0.x,h0.y,h0.z,h0.w,h1.x,h1.y,h1.z,h1.w};
    float bv[8] = {b0.x,b0.y,b0.z,b0.w,b1.x,b1.y,b1.z,b1.w};
    float s_ = 0.f, q_ = 0.f;
    float out8[8];
    #pragma unroll
    for (int j = 0; j < 8; j++) {
        float v  = acc[j] + bv[j];
        float el = v > 0.f ? v : (__expf(v) - 1.f);
        float t  = hv[j] + el;
        out8[j] = t; s_ += t; q_ += t*t;
    }
    __stcs((float4*)ph,     make_float4(out8[0],out8[1],out8[2],out8[3]));
    __stcs((float4*)(ph+4), make_float4(out8[4],out8[5],out8[6],out8[7]));
    #pragma unroll
    for (int off = 16; off; off >>= 1) {
        s_ += __shfl_down_sync(0xffffffffu, s_, off);
        q_ += __shfl_down_sync(0xffffffffu, q_, off);
    }
    __shared__ float ss[8], sq[8];
    int w = threadIdx.x >> 5;
    if (lane == 0) { ss[w] = s_; sq[w] = q_; }
    __syncthreads();
    if (threadIdx.x == 0) {
        float S = 0.f, Q = 0.f;
        #pragma unroll
        for (int i = 0; i < 8; i++) { S += ss[i]; Q += sq[i]; }
        atomicAdd(&g_red[0], (double)S);
        atomicAdd(&g_red[1], (double)Q);
    }
}

__global__ void k_norm(const float* __restrict__ lnw, const float* __restrict__ lnb){
    int idx = blockIdx.x*blockDim.x + threadIdx.x;
    if (idx >= TOT_H) return;
    int c = idx & (HID-1);
    double M  = (double)TOT_H;
    double mu = g_red[0] / M;
    double var = g_red[1] / M - mu*mu;
    if (var < 0.0) var = 0.0;
    float rs = (float)(1.0 / (sqrt(var) + 1e-5));
    float v = __ldcs(&g_h[idx]);
    __stcs(&g_h[idx], (v - (float)mu) * rs * lnw[c] + lnb[c]);
}

// ---------------- launcher ---------------------------------------------------
extern "C" void kernel_launch(void* const* d_in, const int* in_sizes, int n_in,
                              void* d_out, int out_size)
{
    const float* x     = (const float*)d_in[0];
    const int*   ei    = (const int*)  d_in[1];
    const float* ea    = (const float*)d_in[2];
    const float* w_in  = (const float*)d_in[3];
    const float* b_in  = (const float*)d_in[4];
    const float* wl    = (const float*)d_in[5];
    const float* wr    = (const float*)d_in[6];
    const float* we    = (const float*)d_in[7];
    const float* att   = (const float*)d_in[8];
    const float* bconv = (const float*)d_in[9];
    const float* lnw   = (const float*)d_in[10];
    const float* lnb   = (const float*)d_in[11];
    const float* wout  = (const float*)d_in[12];
    const float* bout  = (const float*)d_in[13];
    float* out = (float*)d_out;
    const int* srcA = ei;
    const int* dstA = ei + NE;

    float *p_h, *p_winT, *p_wcatT, *p_woutT;
    __half* p_xlrh;
    int* p_degi;
    cudaGetSymbolAddress((void**)&p_h,     g_h);
    cudaGetSymbolAddress((void**)&p_xlrh,  g_xlrh);
    cudaGetSymbolAddress((void**)&p_degi,  g_degi);
    cudaGetSymbolAddress((void**)&p_winT,  g_winT);
    cudaGetSymbolAddress((void**)&p_wcatT, g_wcatT);
    cudaGetSymbolAddress((void**)&p_woutT, g_woutT);

    dim3 gIn (HID/128, (N_NODES + 127)/128);
    dim3 gXlr(512/128, (N_NODES + 127)/128);

    // launch index 3 = the big N=512 tgemm (profiled slot)
    k_transpose<<<dim3(HID/32, DIN/32), 256>>>(w_in, p_winT, DIN, HID);
    tgemm<<<gIn, 256>>>(x, p_winT, b_in, p_h, nullptr, N_NODES, DIN, HID, 1);
    k_transcat<<<dim3(8, 8, 2), 256>>>(wl, wr);
    tgemm<<<gXlr, 256>>>(p_h, p_wcatT, nullptr, nullptr, p_xlrh, N_NODES, HID, 512, 0);

    // edge preprocessing + CSR
    k_zero_i<<<(N_NODES + 511)/512, 512>>>(p_degi, N_NODES);
    k_degc<<<(NE + 255)/256, 256>>>(dstA);
    k_scan<<<1, 1024>>>();
    k_scatter<<<(ETOT + 255)/256, 256>>>(srcA, dstA);
    k_eafuse<<<N_NODES/8, 256>>>(ea);
    k_transpose<<<dim3(HID/32, HID/32), 256>>>(wout, p_woutT, HID, HID);

    for (int l = 0; l < NLAYER; l++) {
        if (l > 0) {
            k_transcat<<<dim3(8, 8, 2), 256>>>(wl + (size_t)l*HID*HID,
                                               wr + (size_t)l*HID*HID);
            tgemm<<<gXlr, 256>>>(p_h, p_wcatT, nullptr, nullptr, p_xlrh,
                                 N_NODES, HID, 512, 0);
        }
        k_weT<<<(HID*EDIM + 255)/256, 256>>>(we + (size_t)l*EDIM*HID);
        k_eplogits<<<(ETOT + 127)/128, 256>>>(att + (size_t)l*HEADS*CDIM);
        k_nodeagg<<<N_NODES/8, 256>>>(bconv + (size_t)l*HID);
        k_norm<<<TOT_H/256, 256>>>(lnw + (size_t)l*HID, lnb + (size_t)l*HID);
    }
    tgemm<<<gIn, 256>>>(p_h, p_woutT, bout, out, nullptr, N_NODES, HID, HID, 0);
}

// round 14
// speedup vs baseline: 2.5218x; 2.3804x over previous
#include <cuda_runtime.h>
#include <cuda_fp16.h>
#include <math.h>
#include <stdint.h>

#define N_NODES 50000
#define NE      800000
#define ETOT    850000
#define DIN     384
#define HID     256
#define HEADS   4
#define CDIM    64
#define EDIM    32
#define NLAYER  2
#define SLOPE   0.2f
#define TOT_H   (N_NODES*HID)

// ---------------- scratch ----------------------------------------------------
__device__ float    g_h   [(size_t)N_NODES*HID];
__device__ __half   g_xlrh[(size_t)N_NODES*512];    // fp16 xl|xr (51 MB)
__device__ int      g_degi[N_NODES];
__device__ float    g_logits[(size_t)ETOT*HEADS];   // CSR order; later holds exp(logit)
__device__ int      g_csr_ptr[N_NODES+1];
__device__ int      g_cursor [N_NODES];
__device__ int      g_csr_e [ETOT];
__device__ int      g_csr_s [ETOT];
__device__ int      g_csr_d [ETOT];
__device__ __half   g_each [(size_t)ETOT*EDIM];  // ea2 CSR order, fp16 (54 MB)
__device__ float    g_winT [(size_t)HID*DIN];
__device__ float    g_wcatT[(size_t)512*HID];
__device__ float    g_weT  [(size_t)HID*EDIM];   // [n_frag][k] tf32, col-permuted
__device__ float    g_woutT[(size_t)HID*HID];
__device__ double   g_redL[2][2];                // per-layer LN sum/sumsq

// ---------------- helpers ----------------------------------------------------
__device__ __forceinline__ float lrelu(float x){ return x > 0.f ? x : SLOPE*x; }
__device__ __forceinline__ float sel4(float4 v, int h){
    return h==0 ? v.x : (h==1 ? v.y : (h==2 ? v.z : v.w));
}
__device__ __forceinline__ uint32_t f2tf(float f){
    uint32_t u; asm("cvt.rna.tf32.f32 %0, %1;" : "=r"(u) : "f"(f)); return u;
}
__device__ __forceinline__ float tfF(float f){ return __uint_as_float(f2tf(f)); }
__device__ __forceinline__ uint32_t sptr(const void* p){
    return (uint32_t)__cvta_generic_to_shared(p);
}
__device__ __forceinline__ void mma8(float* c, const uint4& a, uint32_t b0, uint32_t b1){
    asm volatile("mma.sync.aligned.m16n8k8.row.col.f32.tf32.tf32.f32 "
        "{%0,%1,%2,%3}, {%4,%5,%6,%7}, {%8,%9}, {%0,%1,%2,%3};"
        : "+f"(c[0]), "+f"(c[1]), "+f"(c[2]), "+f"(c[3])
        : "r"(a.x), "r"(a.y), "r"(a.z), "r"(a.w), "r"(b0), "r"(b1));
}
#define LDSM4(d, addr) \
    asm volatile("ldmatrix.sync.aligned.m8n8.x4.shared.b16 {%0,%1,%2,%3}, [%4];" \
        : "=r"((d).x), "=r"((d).y), "=r"((d).z), "=r"((d).w) : "r"(addr))

// LN affine params from reduction: h' = h*sc + bs
__device__ __forceinline__ void ln_params(const double* red, double* mu_o, double* rs_o){
    double M  = (double)TOT_H;
    double mu = red[0] / M;
    double var = red[1] / M - mu*mu;
    if (var < 0.0) var = 0.0;
    *mu_o = mu;
    *rs_o = 1.0 / (sqrt(var) + 1e-5);
}

// ---------------- setup ------------------------------------------------------
__global__ void k_zero_i(int* p, int n){
    int i = blockIdx.x*blockDim.x + threadIdx.x;
    if (i < n) p[i] = 0;
}
__global__ void k_degc(const int* __restrict__ dst){
    int t = blockIdx.x*blockDim.x + threadIdx.x;
    if (t < NE) atomicAdd(&g_degi[dst[t]], 1);
}

__global__ void k_scan(){
    __shared__ int wsum[32];
    int tid = threadIdx.x, lane = tid & 31, w = tid >> 5;
    int carry = 0;
    if (tid == 0) {
        g_csr_ptr[0] = 0;
        g_redL[0][0] = 0.0; g_redL[0][1] = 0.0;
        g_redL[1][0] = 0.0; g_redL[1][1] = 0.0;
    }
    for (int base = 0; base < N_NODES; base += 1024) {
        int i = base + tid;
        int v = (i < N_NODES) ? (g_degi[i] + 1) : 0;
        int x = v;
        #pragma unroll
        for (int off = 1; off < 32; off <<= 1) {
            int nb = __shfl_up_sync(0xffffffffu, x, off);
            if (lane >= off) x += nb;
        }
        if (lane == 31) wsum[w] = x;
        __syncthreads();
        if (w == 0) {
            int y = wsum[lane];
            #pragma unroll
            for (int off = 1; off < 32; off <<= 1) {
                int nb = __shfl_up_sync(0xffffffffu, y, off);
                if (lane >= off) y += nb;
            }
            wsum[lane] = y;
        }
        __syncthreads();
        int add  = (w > 0) ? wsum[w-1] : 0;
        int incl = carry + add + x;
        if (i < N_NODES) { g_csr_ptr[i+1] = incl; g_cursor[i] = incl - v; }
        carry += wsum[31];
        __syncthreads();
    }
}
__global__ void k_scatter(const int* __restrict__ src, const int* __restrict__ dst){
    int t = blockIdx.x*blockDim.x + threadIdx.x;
    if (t >= ETOT) return;
    int s, d;
    if (t < NE) { s = src[t]; d = dst[t]; } else { s = t - NE; d = s; }
    int pos = atomicAdd(&g_cursor[d], 1);
    g_csr_e[pos] = t;
    g_csr_s[pos] = s;
    g_csr_d[pos] = d;
}

// fused: self-loop mean + CSR-ordered fp16 ea tensor (one ea pass, prefetched)
__global__ __launch_bounds__(256) void k_eafuse(const float* __restrict__ ea){
    int n = (blockIdx.x*256 + threadIdx.x) >> 5;
    int lane = threadIdx.x & 31;
    int p0 = g_csr_ptr[n], p1 = g_csr_ptr[n+1];
    float sum = 0.f; int deg = 0; int selfpos = p0;
    int e_next = g_csr_e[p0];
    for (int pos = p0; pos < p1; pos++) {
        int e = e_next;
        if (pos + 1 < p1) e_next = g_csr_e[pos+1];
        if (e < NE) {
            float v = __ldcs(ea + (size_t)e*EDIM + lane);
            sum += v; deg++;
            g_each[(size_t)pos*EDIM + lane] = __float2half_rn(v);
        } else selfpos = pos;
    }
    float mean = sum / fmaxf((float)deg, 1.f);
    g_each[(size_t)selfpos*EDIM + lane] = __float2half_rn(mean);
}

// ---------------- weight prep ------------------------------------------------
__global__ void k_transpose(const float* __restrict__ in, float* __restrict__ out,
                            int K, int N){
    __shared__ float t[32][33];
    int kb = blockIdx.y*32, nb = blockIdx.x*32;
    int tx = threadIdx.x & 31, ty = threadIdx.x >> 5;
    #pragma unroll
    for (int i = ty; i < 32; i += 8)
        t[i][tx] = in[(size_t)(kb+i)*N + nb + tx];
    __syncthreads();
    #pragma unroll
    for (int i = ty; i < 32; i += 8)
        out[(size_t)(nb+i)*K + kb + tx] = tfF(t[tx][i]);
}
__global__ void k_transcat(const float* __restrict__ wl, const float* __restrict__ wr){
    __shared__ float t[32][33];
    const float* in = blockIdx.z ? wr : wl;
    float* out = g_wcatT + (size_t)blockIdx.z*HID*HID;
    int kb = blockIdx.y*32, nb = blockIdx.x*32;
    int tx = threadIdx.x & 31, ty = threadIdx.x >> 5;
    #pragma unroll
    for (int i = ty; i < 32; i += 8)
        t[i][tx] = in[(size_t)(kb+i)*HID + nb + tx];
    __syncthreads();
    #pragma unroll
    for (int i = ty; i < 32; i += 8)
        out[(size_t)(nb+i)*HID + kb + tx] = tfF(t[tx][i]);
}
// fragment (j=2t+p, q, pair) -> actual col = half*128 + hh*64 + t*16 + q*4 + p*2 + pair
__global__ void k_weT(const float* __restrict__ we){
    int t = blockIdx.x*blockDim.x + threadIdx.x;
    if (t >= HID*EDIM) return;
    int n_f = t >> 5, k = t & 31;
    int half = n_f >> 7, rem = n_f & 127;
    int hh  = rem >> 6;
    int jm  = (rem >> 3) & 7;
    int low = rem & 7, qq = low >> 1, pair = low & 1;
    int tt = jm >> 1, p = jm & 1;
    int a = half*128 + hh*64 + tt*16 + qq*4 + p*2 + pair;
    g_weT[t] = tfF(we[(size_t)k*HID + a]);
}

// ---------------- TF32 LDSM GEMM, optional fused LN on A ---------------------
// If lnw != null: A'[n,k] = A[n,k]*sc[k] + bs[k], sc = rs*lnw[k],
// bs = lnb[k] - mu*sc (mu, rs from red[]).
#define APAD 20
__global__ __launch_bounds__(256) void tgemm(
    const float* __restrict__ A, const float* __restrict__ Bt,
    const float* __restrict__ bias, float* __restrict__ C,
    __half* __restrict__ Ch,
    const float* __restrict__ lnw, const float* __restrict__ lnb,
    const double* __restrict__ red,
    int M, int K, int Nn, int act)
{
    __shared__ float As[2][128*APAD];
    __shared__ float Bs[2][128*APAD];
    __shared__ float sTab[384], bTab[384];
    const int tid = threadIdx.x, lane = tid & 31, wid = tid >> 5;
    const int wm = (wid & 1)*64, wn = (wid >> 1)*32;
    const int cRow = blockIdx.y*128, cCol = blockIdx.x*128;
    const int r0 = tid >> 2, q0 = tid & 3;
    const bool doNorm = (lnw != nullptr);

    if (doNorm) {
        double mu, rs;
        ln_params(red, &mu, &rs);
        for (int k = tid; k < K; k += 256) {
            float sc = (float)rs * lnw[k];
            sTab[k] = sc;
            bTab[k] = lnb[k] - (float)mu * sc;
        }
    }
    __syncthreads();

    const int aoff = ((wm + (lane & 15))*APAD + ((lane >> 4) << 2))*4;
    const int boff = ((wn + (lane & 15))*APAD + ((lane >> 4) << 2))*4;

    float acc[4][4][4];
    #pragma unroll
    for (int i = 0; i < 4; i++)
        #pragma unroll
        for (int j = 0; j < 4; j++)
            #pragma unroll
            for (int v = 0; v < 4; v++) acc[i][j][v] = 0.f;

    float4 aR0, aR1, bR0, bR1;
#define LDG_TILE(kt) { \
    int gr0 = cRow + r0, gr1 = gr0 + 64; \
    aR0 = (gr0 < M) ? *(const float4*)(A + (size_t)gr0*K + (kt) + q0*4) : make_float4(0,0,0,0); \
    aR1 = (gr1 < M) ? *(const float4*)(A + (size_t)gr1*K + (kt) + q0*4) : make_float4(0,0,0,0); \
    if (doNorm) { \
        float4 sc = *(const float4*)(sTab + (kt) + q0*4); \
        float4 bs = *(const float4*)(bTab + (kt) + q0*4); \
        aR0.x = aR0.x*sc.x + bs.x; aR0.y = aR0.y*sc.y + bs.y; \
        aR0.z = aR0.z*sc.z + bs.z; aR0.w = aR0.w*sc.w + bs.w; \
        aR1.x = aR1.x*sc.x + bs.x; aR1.y = aR1.y*sc.y + bs.y; \
        aR1.z = aR1.z*sc.z + bs.z; aR1.w = aR1.w*sc.w + bs.w; \
    } \
    bR0 = *(const float4*)(Bt + (size_t)(cCol + r0)*K + (kt) + q0*4); \
    bR1 = *(const float4*)(Bt + (size_t)(cCol + r0 + 64)*K + (kt) + q0*4); }
#define STS_TILE(b) { \
    float* pa = &As[b][r0*APAD + q0*4]; \
    *(float4*)pa = make_float4(tfF(aR0.x), tfF(aR0.y), tfF(aR0.z), tfF(aR0.w)); \
    *(float4*)(pa + 64*APAD) = make_float4(tfF(aR1.x), tfF(aR1.y), tfF(aR1.z), tfF(aR1.w)); \
    float* pb = &Bs[b][r0*APAD + q0*4]; \
    *(float4*)pb = bR0; \
    *(float4*)(pb + 64*APAD) = bR1; }
#define COMPUTE(b) { \
    uint32_t ab = sptr(&As[b][0]) + aoff; \
    uint32_t bb = sptr(&Bs[b][0]) + boff; \
    _Pragma("unroll") \
    for (int ks = 0; ks < 2; ks++) { \
        uint4 af0, af1, af2, af3, bf0, bf1; \
        LDSM4(af0, ab + (ks*8)*4); \
        LDSM4(af1, ab + (16*APAD + ks*8)*4); \
        LDSM4(af2, ab + (32*APAD + ks*8)*4); \
        LDSM4(af3, ab + (48*APAD + ks*8)*4); \
        LDSM4(bf0, bb + (ks*8)*4); \
        LDSM4(bf1, bb + (16*APAD + ks*8)*4); \
        mma8(acc[0][0], af0, bf0.x, bf0.z); mma8(acc[0][1], af0, bf0.y, bf0.w); \
        mma8(acc[0][2], af0, bf1.x, bf1.z); mma8(acc[0][3], af0, bf1.y, bf1.w); \
        mma8(acc[1][0], af1, bf0.x, bf0.z); mma8(acc[1][1], af1, bf0.y, bf0.w); \
        mma8(acc[1][2], af1, bf1.x, bf1.z); mma8(acc[1][3], af1, bf1.y, bf1.w); \
        mma8(acc[2][0], af2, bf0.x, bf0.z); mma8(acc[2][1], af2, bf0.y, bf0.w); \
        mma8(acc[2][2], af2, bf1.x, bf1.z); mma8(acc[2][3], af2, bf1.y, bf1.w); \
        mma8(acc[3][0], af3, bf0.x, bf0.z); mma8(acc[3][1], af3, bf0.y, bf0.w); \
        mma8(acc[3][2], af3, bf1.x, bf1.z); mma8(acc[3][3], af3, bf1.y, bf1.w); \
    } }

    LDG_TILE(0);
    STS_TILE(0);
    __syncthreads();
    int buf = 0;
    for (int kt = 16; kt < K; kt += 16) {
        LDG_TILE(kt);
        COMPUTE(buf);
        STS_TILE(buf ^ 1);
        __syncthreads();
        buf ^= 1;
    }
    COMPUTE(buf);

    const int g = lane >> 2, q = lane & 3;
    #pragma unroll
    for (int mf = 0; mf < 4; mf++) {
        int rA = cRow + wm + mf*16 + g;
        #pragma unroll
        for (int nf = 0; nf < 4; nf++) {
            int col = cCol + wn + nf*8 + 2*q;
            float bx = 0.f, by = 0.f;
            if (bias) { float2 bb = *(const float2*)(bias + col); bx = bb.x; by = bb.y; }
            float v0 = acc[mf][nf][0] + bx, v1 = acc[mf][nf][1] + by;
            float v2 = acc[mf][nf][2] + bx, v3 = acc[mf][nf][3] + by;
            if (act == 1) {
                v0 = fmaxf(v0,0.f); v1 = fmaxf(v1,0.f);
                v2 = fmaxf(v2,0.f); v3 = fmaxf(v3,0.f);
            }
            if (Ch) {
                if (rA < M)
                    *(__half2*)(Ch + (size_t)rA*Nn + col) = __floats2half2_rn(v0, v1);
                if (rA+8 < M)
                    *(__half2*)(Ch + (size_t)(rA+8)*Nn + col) = __floats2half2_rn(v2, v3);
            } else {
                if (rA < M)     *(float2*)(C + (size_t)rA*Nn + col)     = make_float2(v0,v1);
                if (rA+8 < M)   *(float2*)(C + (size_t)(rA+8)*Nn + col) = make_float2(v2,v3);
            }
        }
    }
#undef LDG_TILE
#undef STS_TILE
#undef COMPUTE
}

// ---------------- fused ep-GEMM + logits (fp16 ea + fp16 xlr) ----------------
#define EPAD 36
__global__ __launch_bounds__(256) void k_eplogits(const float* __restrict__ attL)
{
    __shared__ float As[128*EPAD];
    __shared__ float Bs[256*EPAD];
    __shared__ int s_src[128], s_dst[128];
    const int tid = threadIdx.x, lane = tid & 31, wid = tid >> 5;
    const int q = lane & 3, g = lane >> 2;
    const int e0 = blockIdx.x * 128;

    for (int i = tid; i < 128; i += 256) {
        int pos = e0 + i, s = 0, d = 0;
        if (pos < ETOT) { s = g_csr_s[pos]; d = g_csr_d[pos]; }
        s_src[i] = s; s_dst[i] = d;
    }
    #pragma unroll
    for (int i = 0; i < 2; i++) {
        int f = tid + i*256;
        int row = f >> 2, q4 = f & 3;
        int pos = e0 + row;
        uint4 raw = make_uint4(0,0,0,0);
        if (pos < ETOT)
            raw = __ldcs((const uint4*)(g_each + (size_t)pos*EDIM + q4*8));
        float2 f0 = __half22float2(*(__half2*)&raw.x);
        float2 f1 = __half22float2(*(__half2*)&raw.y);
        float2 f2 = __half22float2(*(__half2*)&raw.z);
        float2 f3 = __half22float2(*(__half2*)&raw.w);
        *(float4*)(&As[row*EPAD + q4*8])     = make_float4(f0.x,f0.y,f1.x,f1.y);
        *(float4*)(&As[row*EPAD + q4*8 + 4]) = make_float4(f2.x,f2.y,f3.x,f3.y);
    }
    #pragma unroll
    for (int i = 0; i < 8; i++) {
        int f = tid + i*256;
        int row = f >> 3, q8 = f & 7;
        *(float4*)(&Bs[row*EPAD + q8*4]) =
            *(const float4*)(g_weT + (size_t)row*EDIM + q8*4);
    }
    __syncthreads();

    const int aoff = ((wid*16 + (lane & 15))*EPAD + ((lane >> 4) << 2))*4;
    const int boff = (((lane & 15))*EPAD + ((lane >> 4) << 2))*4;
    const int r0l = wid*16 + g, r1l = r0l + 8;
    const int s0 = s_src[r0l], d0 = s_dst[r0l];
    const int s1 = s_src[r1l], d1 = s_dst[r1l];
    const uint32_t ab = sptr(&As[0]) + aoff;
    const uint32_t bb = sptr(&Bs[0]) + boff;

    #pragma unroll
    for (int half = 0; half < 2; half++) {
        float acc[16][4];
        #pragma unroll
        for (int j = 0; j < 16; j++)
            #pragma unroll
            for (int v = 0; v < 4; v++) acc[j][v] = 0.f;
        uint32_t bbh = bb + half*(128*EPAD*4);
        #pragma unroll
        for (int ks = 0; ks < 4; ks++) {
            uint4 a;
            LDSM4(a, ab + (ks*8)*4);
            #pragma unroll
            for (int nt = 0; nt < 8; nt++) {
                uint4 b;
                LDSM4(b, bbh + (nt*16*EPAD + ks*8)*4);
                mma8(acc[nt*2+0], a, b.x, b.z);
                mma8(acc[nt*2+1], a, b.y, b.w);
            }
        }
        float p0h0 = 0.f, p0h1 = 0.f, p1h0 = 0.f, p1h1 = 0.f;
        #pragma unroll
        for (int hh = 0; hh < 2; hh++) {
            #pragma unroll
            for (int t = 0; t < 4; t++) {
                int cb = half*128 + hh*64 + t*16 + q*4;
                float4 at = *(const float4*)(attL + cb);
                uint2 ra0 = *(const uint2*)(g_xlrh + (size_t)s0*512 + cb);
                uint2 rb0 = *(const uint2*)(g_xlrh + (size_t)d0*512 + 256 + cb);
                uint2 ra1 = *(const uint2*)(g_xlrh + (size_t)s1*512 + cb);
                uint2 rb1 = *(const uint2*)(g_xlrh + (size_t)d1*512 + 256 + cb);
                float2 a0l = __half22float2(*(__half2*)&ra0.x);
                float2 a0h = __half22float2(*(__half2*)&ra0.y);
                float2 b0l = __half22float2(*(__half2*)&rb0.x);
                float2 b0h = __half22float2(*(__half2*)&rb0.y);
                float2 a1l = __half22float2(*(__half2*)&ra1.x);
                float2 a1h = __half22float2(*(__half2*)&ra1.y);
                float2 b1l = __half22float2(*(__half2*)&rb1.x);
                float2 b1h = __half22float2(*(__half2*)&rb1.y);
                int ja = hh*8 + 2*t;
                float c0 = lrelu(acc[ja][0]   + a0l.x + b0l.x)*at.x
                         + lrelu(acc[ja][1]   + a0l.y + b0l.y)*at.y
                         + lrelu(acc[ja+1][0] + a0h.x + b0h.x)*at.z
                         + lrelu(acc[ja+1][1] + a0h.y + b0h.y)*at.w;
                float c1 = lrelu(acc[ja][2]   + a1l.x + b1l.x)*at.x
                         + lrelu(acc[ja][3]   + a1l.y + b1l.y)*at.y
                         + lrelu(acc[ja+1][2] + a1h.x + b1h.x)*at.z
                         + lrelu(acc[ja+1][3] + a1h.y + b1h.y)*at.w;
                if (hh == 0) { p0h0 += c0; p1h0 += c1; }
                else         { p0h1 += c0; p1h1 += c1; }
            }
        }
        #pragma unroll
        for (int off = 1; off <= 2; off <<= 1) {
            p0h0 += __shfl_xor_sync(0xffffffffu, p0h0, off);
            p0h1 += __shfl_xor_sync(0xffffffffu, p0h1, off);
            p1h0 += __shfl_xor_sync(0xffffffffu, p1h0, off);
            p1h1 += __shfl_xor_sync(0xffffffffu, p1h1, off);
        }
        if (q == 0) {
            if (e0 + r0l < ETOT) {
                g_logits[(size_t)(e0 + r0l)*HEADS + half*2 + 0] = p0h0;
                g_logits[(size_t)(e0 + r0l)*HEADS + half*2 + 1] = p0h1;
            }
            if (e0 + r1l < ETOT) {
                g_logits[(size_t)(e0 + r1l)*HEADS + half*2 + 0] = p1h0;
                g_logits[(size_t)(e0 + r1l)*HEADS + half*2 + 1] = p1h1;
            }
        }
    }
}

// ---------------- node aggregation (exp-once softmax, fused LN on residual) --
// lnwP==null: residual read raw. Else residual = raw*sc+bs per channel
// (previous layer's LN). Accumulates this layer's sum/sumsq into redO.
__global__ __launch_bounds__(256) void k_nodeagg(
    const float* __restrict__ bconv,
    const float* __restrict__ lnwP, const float* __restrict__ lnbP,
    const double* __restrict__ redP, double* __restrict__ redO)
{
    const int n    = (blockIdx.x*256 + threadIdx.x) >> 5;
    const int lane = threadIdx.x & 31;
    const int p0 = g_csr_ptr[n], p1 = g_csr_ptr[n+1];
    float4 sm = make_float4(0,0,0,0);
    for (int idx = p0 + lane; idx < p1; idx += 32) {
        float4 lg = *(const float4*)(g_logits + (size_t)idx*HEADS);
        float4 ex = make_float4(__expf(lg.x), __expf(lg.y), __expf(lg.z), __expf(lg.w));
        *(float4*)(g_logits + (size_t)idx*HEADS) = ex;
        sm.x += ex.x; sm.y += ex.y; sm.z += ex.z; sm.w += ex.w;
    }
    #pragma unroll
    for (int off = 16; off; off >>= 1) {
        sm.x += __shfl_xor_sync(0xffffffffu, sm.x, off);
        sm.y += __shfl_xor_sync(0xffffffffu, sm.y, off);
        sm.z += __shfl_xor_sync(0xffffffffu, sm.z, off);
        sm.w += __shfl_xor_sync(0xffffffffu, sm.w, off);
    }
    __syncwarp();
    const int head = lane >> 3;
    const float ih = 1.f / (sel4(sm, head) + 1e-16f);
    float acc[8];
    #pragma unroll
    for (int j = 0; j < 8; j++) acc[j] = 0.f;
    int   s_nx   = g_csr_s[p0];
    float4 ex_nx = *(const float4*)(g_logits + (size_t)p0*HEADS);
    uint4  raw_nx = *(const uint4*)(g_xlrh + (size_t)s_nx*512 + lane*8);
    for (int idx = p0; idx < p1; idx++) {
        float4 ex = ex_nx;
        uint4 raw = raw_nx;
        if (idx + 1 < p1) {
            int s2 = g_csr_s[idx+1];
            ex_nx  = *(const float4*)(g_logits + (size_t)(idx+1)*HEADS);
            raw_nx = *(const uint4*)(g_xlrh + (size_t)s2*512 + lane*8);
        }
        float w = sel4(ex, head) * ih;
        float2 f0 = __half22float2(*(__half2*)&raw.x);
        float2 f1 = __half22float2(*(__half2*)&raw.y);
        float2 f2 = __half22float2(*(__half2*)&raw.z);
        float2 f3 = __half22float2(*(__half2*)&raw.w);
        acc[0] += w*f0.x; acc[1] += w*f0.y; acc[2] += w*f1.x; acc[3] += w*f1.y;
        acc[4] += w*f2.x; acc[5] += w*f2.y; acc[6] += w*f3.x; acc[7] += w*f3.y;
    }
    float* ph = g_h + (size_t)n*HID + lane*8;
    float4 h0 = __ldcs((const float4*)ph);
    float4 h1 = __ldcs((const float4*)(ph+4));
    float4 b0 = *(const float4*)(bconv + lane*8);
    float4 b1 = *(const float4*)(bconv + lane*8 + 4);
    float hv[8] = {h0.x,h0.y,h0.z,h0.w,h1.x,h1.y,h1.z,h1.w};
    float bv[8] = {b0.x,b0.y,b0.z,b0.w,b1.x,b1.y,b1.z,b1.w};
    if (lnwP) {
        double mu, rs;
        ln_params(redP, &mu, &rs);
        float4 w0 = *(const float4*)(lnwP + lane*8);
        float4 w1 = *(const float4*)(lnwP + lane*8 + 4);
        float4 l0 = *(const float4*)(lnbP + lane*8);
        float4 l1 = *(const float4*)(lnbP + lane*8 + 4);
        float wv[8] = {w0.x,w0.y,w0.z,w0.w,w1.x,w1.y,w1.z,w1.w};
        float lv[8] = {l0.x,l0.y,l0.z,l0.w,l1.x,l1.y,l1.z,l1.w};
        #pragma unroll
        for (int j = 0; j < 8; j++) {
            float sc = (float)rs * wv[j];
            hv[j] = hv[j]*sc + (lv[j] - (float)mu*sc);
        }
    }
    float s_ = 0.f, q_ = 0.f;
    float out8[8];
    #pragma unroll
    for (int j = 0; j < 8; j++) {
        float v  = acc[j] + bv[j];
        float el = v > 0.f ? v : (__expf(v) - 1.f);
        float t  = hv[j] + el;
        out8[j] = t; s_ += t; q_ += t*t;
    }
    __stcs((float4*)ph,     make_float4(out8[0],out8[1],out8[2],out8[3]));
    __stcs((float4*)(ph+4), make_float4(out8[4],out8[5],out8[6],out8[7]));
    #pragma unroll
    for (int off = 16; off; off >>= 1) {
        s_ += __shfl_down_sync(0xffffffffu, s_, off);
        q_ += __shfl_down_sync(0xffffffffu, q_, off);
    }
    __shared__ float ss[8], sq[8];
    int w = threadIdx.x >> 5;
    if (lane == 0) { ss[w] = s_; sq[w] = q_; }
    __syncthreads();
    if (threadIdx.x == 0) {
        float S = 0.f, Q = 0.f;
        #pragma unroll
        for (int i = 0; i < 8; i++) { S += ss[i]; Q += sq[i]; }
        atomicAdd(&redO[0], (double)S);
        atomicAdd(&redO[1], (double)Q);
    }
}

// ---------------- launcher ---------------------------------------------------
extern "C" void kernel_launch(void* const* d_in, const int* in_sizes, int n_in,
                              void* d_out, int out_size)
{
    const float* x     = (const float*)d_in[0];
    const int*   ei    = (const int*)  d_in[1];
    const float* ea    = (const float*)d_in[2];
    const float* w_in  = (const float*)d_in[3];
    const float* b_in  = (const float*)d_in[4];
    const float* wl    = (const float*)d_in[5];
    const float* wr    = (const float*)d_in[6];
    const float* we    = (const float*)d_in[7];
    const float* att   = (const float*)d_in[8];
    const float* bconv = (const float*)d_in[9];
    const float* lnw   = (const float*)d_in[10];
    const float* lnb   = (const float*)d_in[11];
    const float* wout  = (const float*)d_in[12];
    const float* bout  = (const float*)d_in[13];
    float* out = (float*)d_out;
    const int* srcA = ei;
    const int* dstA = ei + NE;

    float *p_h, *p_winT, *p_wcatT, *p_woutT;
    __half* p_xlrh;
    int* p_degi;
    double* p_red;
    cudaGetSymbolAddress((void**)&p_h,     g_h);
    cudaGetSymbolAddress((void**)&p_xlrh,  g_xlrh);
    cudaGetSymbolAddress((void**)&p_degi,  g_degi);
    cudaGetSymbolAddress((void**)&p_winT,  g_winT);
    cudaGetSymbolAddress((void**)&p_wcatT, g_wcatT);
    cudaGetSymbolAddress((void**)&p_woutT, g_woutT);
    cudaGetSymbolAddress((void**)&p_red,   g_redL);
    double* redL0 = p_red;
    double* redL1 = p_red + 2;

    dim3 gIn (HID/128, (N_NODES + 127)/128);
    dim3 gXlr(512/128, (N_NODES + 127)/128);

    // launch index 3 = the big N=512 tgemm (profiled slot)
    k_transpose<<<dim3(HID/32, DIN/32), 256>>>(w_in, p_winT, DIN, HID);
    tgemm<<<gIn, 256>>>(x, p_winT, b_in, p_h, nullptr,
                        nullptr, nullptr, nullptr, N_NODES, DIN, HID, 1);
    k_transcat<<<dim3(8, 8, 2), 256>>>(wl, wr);
    tgemm<<<gXlr, 256>>>(p_h, p_wcatT, nullptr, nullptr, p_xlrh,
                         nullptr, nullptr, nullptr, N_NODES, HID, 512, 0);

    // edge preprocessing + CSR
    k_zero_i<<<(N_NODES + 511)/512, 512>>>(p_degi, N_NODES);
    k_degc<<<(NE + 255)/256, 256>>>(dstA);
    k_scan<<<1, 1024>>>();
    k_scatter<<<(ETOT + 255)/256, 256>>>(srcA, dstA);
    k_eafuse<<<N_NODES/8, 256>>>(ea);
    k_transpose<<<dim3(HID/32, HID/32), 256>>>(wout, p_woutT, HID, HID);

    // ---- layer 0 ----
    k_weT<<<(HID*EDIM + 255)/256, 256>>>(we);
    k_eplogits<<<(ETOT + 127)/128, 256>>>(att);
    k_nodeagg<<<N_NODES/8, 256>>>(bconv, nullptr, nullptr, nullptr, redL0);

    // ---- layer 1 ----  (xlr GEMM applies layer-0 LN to h on the fly)
    k_transcat<<<dim3(8, 8, 2), 256>>>(wl + (size_t)HID*HID, wr + (size_t)HID*HID);
    tgemm<<<gXlr, 256>>>(p_h, p_wcatT, nullptr, nullptr, p_xlrh,
                         lnw, lnb, redL0, N_NODES, HID, 512, 0);
    k_weT<<<(HID*EDIM + 255)/256, 256>>>(we + (size_t)EDIM*HID);
    k_eplogits<<<(ETOT + 127)/128, 256>>>(att + (size_t)HEADS*CDIM);
    k_nodeagg<<<N_NODES/8, 256>>>(bconv + HID, lnw, lnb, redL0, redL1);

    // ---- output GEMM applies layer-1 LN on the fly ----
    tgemm<<<gIn, 256>>>(p_h, p_woutT, bout, out, nullptr,
                        lnw + HID, lnb + HID, redL1, N_NODES, HID, HID, 0);
}

// round 15
// speedup vs baseline: 2.5422x; 1.0081x over previous
#include <cuda_runtime.h>
#include <cuda_fp16.h>
#include <math.h>
#include <stdint.h>

#define N_NODES 50000
#define NE      800000
#define ETOT    850000
#define DIN     384
#define HID     256
#define HEADS   4
#define CDIM    64
#define EDIM    32
#define NLAYER  2
#define SLOPE   0.2f
#define TOT_H   (N_NODES*HID)

// ---------------- scratch ----------------------------------------------------
__device__ float    g_h   [(size_t)N_NODES*HID];
__device__ __half   g_xlrh[(size_t)N_NODES*512];    // fp16 xl|xr (51 MB)
__device__ int      g_degi[N_NODES];
__device__ float    g_logits[(size_t)ETOT*HEADS];   // CSR order, holds exp(logit)
__device__ int      g_csr_ptr[N_NODES+1];
__device__ int      g_cursor [N_NODES];
__device__ int      g_csr_e [ETOT];
__device__ int      g_csr_s [ETOT];
__device__ int      g_csr_d [ETOT];
__device__ __half   g_each [(size_t)ETOT*EDIM];  // ea2 CSR order, fp16 (54 MB)
__device__ float    g_winT [(size_t)HID*DIN];
__device__ float    g_wcatT[(size_t)512*HID];
__device__ float    g_weT  [(size_t)HID*EDIM];   // [n_frag][k] tf32, col-permuted
__device__ float    g_woutT[(size_t)HID*HID];
__device__ double   g_redL[2][2];                // per-layer LN sum/sumsq

// ---------------- helpers ----------------------------------------------------
__device__ __forceinline__ float lrelu(float x){ return x > 0.f ? x : SLOPE*x; }
__device__ __forceinline__ float sel4(float4 v, int h){
    return h==0 ? v.x : (h==1 ? v.y : (h==2 ? v.z : v.w));
}
__device__ __forceinline__ uint32_t f2tf(float f){
    uint32_t u; asm("cvt.rna.tf32.f32 %0, %1;" : "=r"(u) : "f"(f)); return u;
}
__device__ __forceinline__ float tfF(float f){ return __uint_as_float(f2tf(f)); }
__device__ __forceinline__ uint32_t sptr(const void* p){
    return (uint32_t)__cvta_generic_to_shared(p);
}
__device__ __forceinline__ void mma8(float* c, const uint4& a, uint32_t b0, uint32_t b1){
    asm volatile("mma.sync.aligned.m16n8k8.row.col.f32.tf32.tf32.f32 "
        "{%0,%1,%2,%3}, {%4,%5,%6,%7}, {%8,%9}, {%0,%1,%2,%3};"
        : "+f"(c[0]), "+f"(c[1]), "+f"(c[2]), "+f"(c[3])
        : "r"(a.x), "r"(a.y), "r"(a.z), "r"(a.w), "r"(b0), "r"(b1));
}
#define LDSM4(d, addr) \
    asm volatile("ldmatrix.sync.aligned.m8n8.x4.shared.b16 {%0,%1,%2,%3}, [%4];" \
        : "=r"((d).x), "=r"((d).y), "=r"((d).z), "=r"((d).w) : "r"(addr))

__device__ __forceinline__ void ln_params(const double* red, double* mu_o, double* rs_o){
    double M  = (double)TOT_H;
    double mu = red[0] / M;
    double var = red[1] / M - mu*mu;
    if (var < 0.0) var = 0.0;
    *mu_o = mu;
    *rs_o = 1.0 / (sqrt(var) + 1e-5);
}

// ---------------- setup ------------------------------------------------------
__global__ void k_zero_i(int* p, int n){
    int i = blockIdx.x*blockDim.x + threadIdx.x;
    if (i < n) p[i] = 0;
}
__global__ void k_degc(const int* __restrict__ dst){
    int t = blockIdx.x*blockDim.x + threadIdx.x;
    if (t < NE) atomicAdd(&g_degi[dst[t]], 1);
}

__global__ void k_scan(){
    __shared__ int wsum[32];
    int tid = threadIdx.x, lane = tid & 31, w = tid >> 5;
    int carry = 0;
    if (tid == 0) {
        g_csr_ptr[0] = 0;
        g_redL[0][0] = 0.0; g_redL[0][1] = 0.0;
        g_redL[1][0] = 0.0; g_redL[1][1] = 0.0;
    }
    for (int base = 0; base < N_NODES; base += 1024) {
        int i = base + tid;
        int v = (i < N_NODES) ? (g_degi[i] + 1) : 0;
        int x = v;
        #pragma unroll
        for (int off = 1; off < 32; off <<= 1) {
            int nb = __shfl_up_sync(0xffffffffu, x, off);
            if (lane >= off) x += nb;
        }
        if (lane == 31) wsum[w] = x;
        __syncthreads();
        if (w == 0) {
            int y = wsum[lane];
            #pragma unroll
            for (int off = 1; off < 32; off <<= 1) {
                int nb = __shfl_up_sync(0xffffffffu, y, off);
                if (lane >= off) y += nb;
            }
            wsum[lane] = y;
        }
        __syncthreads();
        int add  = (w > 0) ? wsum[w-1] : 0;
        int incl = carry + add + x;
        if (i < N_NODES) { g_csr_ptr[i+1] = incl; g_cursor[i] = incl - v; }
        carry += wsum[31];
        __syncthreads();
    }
}
__global__ void k_scatter(const int* __restrict__ src, const int* __restrict__ dst){
    int t = blockIdx.x*blockDim.x + threadIdx.x;
    if (t >= ETOT) return;
    int s, d;
    if (t < NE) { s = src[t]; d = dst[t]; } else { s = t - NE; d = s; }
    int pos = atomicAdd(&g_cursor[d], 1);
    g_csr_e[pos] = t;
    g_csr_s[pos] = s;
    g_csr_d[pos] = d;
}

// fused: self-loop mean + CSR-ordered fp16 ea tensor
__global__ __launch_bounds__(256) void k_eafuse(const float* __restrict__ ea){
    int n = (blockIdx.x*256 + threadIdx.x) >> 5;
    int lane = threadIdx.x & 31;
    int p0 = g_csr_ptr[n], p1 = g_csr_ptr[n+1];
    float sum = 0.f; int deg = 0; int selfpos = p0;
    int e_next = g_csr_e[p0];
    for (int pos = p0; pos < p1; pos++) {
        int e = e_next;
        if (pos + 1 < p1) e_next = g_csr_e[pos+1];
        if (e < NE) {
            float v = __ldcs(ea + (size_t)e*EDIM + lane);
            sum += v; deg++;
            g_each[(size_t)pos*EDIM + lane] = __float2half_rn(v);
        } else selfpos = pos;
    }
    float mean = sum / fmaxf((float)deg, 1.f);
    g_each[(size_t)selfpos*EDIM + lane] = __float2half_rn(mean);
}

// ---------------- weight prep ------------------------------------------------
__global__ void k_transpose(const float* __restrict__ in, float* __restrict__ out,
                            int K, int N){
    __shared__ float t[32][33];
    int kb = blockIdx.y*32, nb = blockIdx.x*32;
    int tx = threadIdx.x & 31, ty = threadIdx.x >> 5;
    #pragma unroll
    for (int i = ty; i < 32; i += 8)
        t[i][tx] = in[(size_t)(kb+i)*N + nb + tx];
    __syncthreads();
    #pragma unroll
    for (int i = ty; i < 32; i += 8)
        out[(size_t)(nb+i)*K + kb + tx] = tfF(t[tx][i]);
}
__global__ void k_transcat(const float* __restrict__ wl, const float* __restrict__ wr){
    __shared__ float t[32][33];
    const float* in = blockIdx.z ? wr : wl;
    float* out = g_wcatT + (size_t)blockIdx.z*HID*HID;
    int kb = blockIdx.y*32, nb = blockIdx.x*32;
    int tx = threadIdx.x & 31, ty = threadIdx.x >> 5;
    #pragma unroll
    for (int i = ty; i < 32; i += 8)
        t[i][tx] = in[(size_t)(kb+i)*HID + nb + tx];
    __syncthreads();
    #pragma unroll
    for (int i = ty; i < 32; i += 8)
        out[(size_t)(nb+i)*HID + kb + tx] = tfF(t[tx][i]);
}
// fragment (j=2t+p, q, pair) -> actual col = half*128 + hh*64 + t*16 + q*4 + p*2 + pair
__global__ void k_weT(const float* __restrict__ we){
    int t = blockIdx.x*blockDim.x + threadIdx.x;
    if (t >= HID*EDIM) return;
    int n_f = t >> 5, k = t & 31;
    int half = n_f >> 7, rem = n_f & 127;
    int hh  = rem >> 6;
    int jm  = (rem >> 3) & 7;
    int low = rem & 7, qq = low >> 1, pair = low & 1;
    int tt = jm >> 1, p = jm & 1;
    int a = half*128 + hh*64 + tt*16 + qq*4 + p*2 + pair;
    g_weT[t] = tfF(we[(size_t)k*HID + a]);
}

// ---------------- TF32 LDSM GEMM, optional fused LN on A ---------------------
#define APAD 20
__global__ __launch_bounds__(256) void tgemm(
    const float* __restrict__ A, const float* __restrict__ Bt,
    const float* __restrict__ bias, float* __restrict__ C,
    __half* __restrict__ Ch,
    const float* __restrict__ lnw, const float* __restrict__ lnb,
    const double* __restrict__ red,
    int M, int K, int Nn, int act)
{
    __shared__ float As[2][128*APAD];
    __shared__ float Bs[2][128*APAD];
    __shared__ float sTab[384], bTab[384];
    const int tid = threadIdx.x, lane = tid & 31, wid = tid >> 5;
    const int wm = (wid & 1)*64, wn = (wid >> 1)*32;
    const int cRow = blockIdx.y*128, cCol = blockIdx.x*128;
    const int r0 = tid >> 2, q0 = tid & 3;
    const bool doNorm = (lnw != nullptr);

    if (doNorm) {
        double mu, rs;
        ln_params(red, &mu, &rs);
        for (int k = tid; k < K; k += 256) {
            float sc = (float)rs * lnw[k];
            sTab[k] = sc;
            bTab[k] = lnb[k] - (float)mu * sc;
        }
    }
    __syncthreads();

    const int aoff = ((wm + (lane & 15))*APAD + ((lane >> 4) << 2))*4;
    const int boff = ((wn + (lane & 15))*APAD + ((lane >> 4) << 2))*4;

    float acc[4][4][4];
    #pragma unroll
    for (int i = 0; i < 4; i++)
        #pragma unroll
        for (int j = 0; j < 4; j++)
            #pragma unroll
            for (int v = 0; v < 4; v++) acc[i][j][v] = 0.f;

    float4 aR0, aR1, bR0, bR1;
#define LDG_TILE(kt) { \
    int gr0 = cRow + r0, gr1 = gr0 + 64; \
    aR0 = (gr0 < M) ? *(const float4*)(A + (size_t)gr0*K + (kt) + q0*4) : make_float4(0,0,0,0); \
    aR1 = (gr1 < M) ? *(const float4*)(A + (size_t)gr1*K + (kt) + q0*4) : make_float4(0,0,0,0); \
    if (doNorm) { \
        float4 sc = *(const float4*)(sTab + (kt) + q0*4); \
        float4 bs = *(const float4*)(bTab + (kt) + q0*4); \
        aR0.x = aR0.x*sc.x + bs.x; aR0.y = aR0.y*sc.y + bs.y; \
        aR0.z = aR0.z*sc.z + bs.z; aR0.w = aR0.w*sc.w + bs.w; \
        aR1.x = aR1.x*sc.x + bs.x; aR1.y = aR1.y*sc.y + bs.y; \
        aR1.z = aR1.z*sc.z + bs.z; aR1.w = aR1.w*sc.w + bs.w; \
    } \
    bR0 = *(const float4*)(Bt + (size_t)(cCol + r0)*K + (kt) + q0*4); \
    bR1 = *(const float4*)(Bt + (size_t)(cCol + r0 + 64)*K + (kt) + q0*4); }
#define STS_TILE(b) { \
    float* pa = &As[b][r0*APAD + q0*4]; \
    *(float4*)pa = make_float4(tfF(aR0.x), tfF(aR0.y), tfF(aR0.z), tfF(aR0.w)); \
    *(float4*)(pa + 64*APAD) = make_float4(tfF(aR1.x), tfF(aR1.y), tfF(aR1.z), tfF(aR1.w)); \
    float* pb = &Bs[b][r0*APAD + q0*4]; \
    *(float4*)pb = bR0; \
    *(float4*)(pb + 64*APAD) = bR1; }
#define COMPUTE(b) { \
    uint32_t ab = sptr(&As[b][0]) + aoff; \
    uint32_t bb = sptr(&Bs[b][0]) + boff; \
    _Pragma("unroll") \
    for (int ks = 0; ks < 2; ks++) { \
        uint4 af0, af1, af2, af3, bf0, bf1; \
        LDSM4(af0, ab + (ks*8)*4); \
        LDSM4(af1, ab + (16*APAD + ks*8)*4); \
        LDSM4(af2, ab + (32*APAD + ks*8)*4); \
        LDSM4(af3, ab + (48*APAD + ks*8)*4); \
        LDSM4(bf0, bb + (ks*8)*4); \
        LDSM4(bf1, bb + (16*APAD + ks*8)*4); \
        mma8(acc[0][0], af0, bf0.x, bf0.z); mma8(acc[0][1], af0, bf0.y, bf0.w); \
        mma8(acc[0][2], af0, bf1.x, bf1.z); mma8(acc[0][3], af0, bf1.y, bf1.w); \
        mma8(acc[1][0], af1, bf0.x, bf0.z); mma8(acc[1][1], af1, bf0.y, bf0.w); \
        mma8(acc[1][2], af1, bf1.x, bf1.z); mma8(acc[1][3], af1, bf1.y, bf1.w); \
        mma8(acc[2][0], af2, bf0.x, bf0.z); mma8(acc[2][1], af2, bf0.y, bf0.w); \
        mma8(acc[2][2], af2, bf1.x, bf1.z); mma8(acc[2][3], af2, bf1.y, bf1.w); \
        mma8(acc[3][0], af3, bf0.x, bf0.z); mma8(acc[3][1], af3, bf0.y, bf0.w); \
        mma8(acc[3][2], af3, bf1.x, bf1.z); mma8(acc[3][3], af3, bf1.y, bf1.w); \
    } }

    LDG_TILE(0);
    STS_TILE(0);
    __syncthreads();
    int buf = 0;
    for (int kt = 16; kt < K; kt += 16) {
        LDG_TILE(kt);
        COMPUTE(buf);
        STS_TILE(buf ^ 1);
        __syncthreads();
        buf ^= 1;
    }
    COMPUTE(buf);

    const int g = lane >> 2, q = lane & 3;
    #pragma unroll
    for (int mf = 0; mf < 4; mf++) {
        int rA = cRow + wm + mf*16 + g;
        #pragma unroll
        for (int nf = 0; nf < 4; nf++) {
            int col = cCol + wn + nf*8 + 2*q;
            float bx = 0.f, by = 0.f;
            if (bias) { float2 bb = *(const float2*)(bias + col); bx = bb.x; by = bb.y; }
            float v0 = acc[mf][nf][0] + bx, v1 = acc[mf][nf][1] + by;
            float v2 = acc[mf][nf][2] + bx, v3 = acc[mf][nf][3] + by;
            if (act == 1) {
                v0 = fmaxf(v0,0.f); v1 = fmaxf(v1,0.f);
                v2 = fmaxf(v2,0.f); v3 = fmaxf(v3,0.f);
            }
            if (Ch) {
                if (rA < M)
                    *(__half2*)(Ch + (size_t)rA*Nn + col) = __floats2half2_rn(v0, v1);
                if (rA+8 < M)
                    *(__half2*)(Ch + (size_t)(rA+8)*Nn + col) = __floats2half2_rn(v2, v3);
            } else {
                if (rA < M)     *(float2*)(C + (size_t)rA*Nn + col)     = make_float2(v0,v1);
                if (rA+8 < M)   *(float2*)(C + (size_t)(rA+8)*Nn + col) = make_float2(v2,v3);
            }
        }
    }
#undef LDG_TILE
#undef STS_TILE
#undef COMPUTE
}

// ---------------- fused ep-GEMM + logits; stores exp(logit) ------------------
#define EPAD 36
__global__ __launch_bounds__(256) void k_eplogits(const float* __restrict__ attL)
{
    __shared__ float As[128*EPAD];
    __shared__ float Bs[256*EPAD];
    __shared__ int s_src[128], s_dst[128];
    const int tid = threadIdx.x, lane = tid & 31, wid = tid >> 5;
    const int q = lane & 3, g = lane >> 2;
    const int e0 = blockIdx.x * 128;

    for (int i = tid; i < 128; i += 256) {
        int pos = e0 + i, s = 0, d = 0;
        if (pos < ETOT) { s = g_csr_s[pos]; d = g_csr_d[pos]; }
        s_src[i] = s; s_dst[i] = d;
    }
    #pragma unroll
    for (int i = 0; i < 2; i++) {
        int f = tid + i*256;
        int row = f >> 2, q4 = f & 3;
        int pos = e0 + row;
        uint4 raw = make_uint4(0,0,0,0);
        if (pos < ETOT)
            raw = __ldcs((const uint4*)(g_each + (size_t)pos*EDIM + q4*8));
        float2 f0 = __half22float2(*(__half2*)&raw.x);
        float2 f1 = __half22float2(*(__half2*)&raw.y);
        float2 f2 = __half22float2(*(__half2*)&raw.z);
        float2 f3 = __half22float2(*(__half2*)&raw.w);
        *(float4*)(&As[row*EPAD + q4*8])     = make_float4(f0.x,f0.y,f1.x,f1.y);
        *(float4*)(&As[row*EPAD + q4*8 + 4]) = make_float4(f2.x,f2.y,f3.x,f3.y);
    }
    #pragma unroll
    for (int i = 0; i < 8; i++) {
        int f = tid + i*256;
        int row = f >> 3, q8 = f & 7;
        *(float4*)(&Bs[row*EPAD + q8*4]) =
            *(const float4*)(g_weT + (size_t)row*EDIM + q8*4);
    }
    __syncthreads();

    const int aoff = ((wid*16 + (lane & 15))*EPAD + ((lane >> 4) << 2))*4;
    const int boff = (((lane & 15))*EPAD + ((lane >> 4) << 2))*4;
    const int r0l = wid*16 + g, r1l = r0l + 8;
    const int s0 = s_src[r0l], d0 = s_dst[r0l];
    const int s1 = s_src[r1l], d1 = s_dst[r1l];
    const uint32_t ab = sptr(&As[0]) + aoff;
    const uint32_t bb = sptr(&Bs[0]) + boff;

    #pragma unroll
    for (int half = 0; half < 2; half++) {
        float acc[16][4];
        #pragma unroll
        for (int j = 0; j < 16; j++)
            #pragma unroll
            for (int v = 0; v < 4; v++) acc[j][v] = 0.f;
        uint32_t bbh = bb + half*(128*EPAD*4);
        #pragma unroll
        for (int ks = 0; ks < 4; ks++) {
            uint4 a;
            LDSM4(a, ab + (ks*8)*4);
            #pragma unroll
            for (int nt = 0; nt < 8; nt++) {
                uint4 b;
                LDSM4(b, bbh + (nt*16*EPAD + ks*8)*4);
                mma8(acc[nt*2+0], a, b.x, b.z);
                mma8(acc[nt*2+1], a, b.y, b.w);
            }
        }
        float p0h0 = 0.f, p0h1 = 0.f, p1h0 = 0.f, p1h1 = 0.f;
        #pragma unroll
        for (int hh = 0; hh < 2; hh++) {
            #pragma unroll
            for (int t = 0; t < 4; t++) {
                int cb = half*128 + hh*64 + t*16 + q*4;
                float4 at = *(const float4*)(attL + cb);
                uint2 ra0 = *(const uint2*)(g_xlrh + (size_t)s0*512 + cb);
                uint2 rb0 = *(const uint2*)(g_xlrh + (size_t)d0*512 + 256 + cb);
                uint2 ra1 = *(const uint2*)(g_xlrh + (size_t)s1*512 + cb);
                uint2 rb1 = *(const uint2*)(g_xlrh + (size_t)d1*512 + 256 + cb);
                float2 a0l = __half22float2(*(__half2*)&ra0.x);
                float2 a0h = __half22float2(*(__half2*)&ra0.y);
                float2 b0l = __half22float2(*(__half2*)&rb0.x);
                float2 b0h = __half22float2(*(__half2*)&rb0.y);
                float2 a1l = __half22float2(*(__half2*)&ra1.x);
                float2 a1h = __half22float2(*(__half2*)&ra1.y);
                float2 b1l = __half22float2(*(__half2*)&rb1.x);
                float2 b1h = __half22float2(*(__half2*)&rb1.y);
                int ja = hh*8 + 2*t;
                float c0 = lrelu(acc[ja][0]   + a0l.x + b0l.x)*at.x
                         + lrelu(acc[ja][1]   + a0l.y + b0l.y)*at.y
                         + lrelu(acc[ja+1][0] + a0h.x + b0h.x)*at.z
                         + lrelu(acc[ja+1][1] + a0h.y + b0h.y)*at.w;
                float c1 = lrelu(acc[ja][2]   + a1l.x + b1l.x)*at.x
                         + lrelu(acc[ja][3]   + a1l.y + b1l.y)*at.y
                         + lrelu(acc[ja+1][2] + a1h.x + b1h.x)*at.z
                         + lrelu(acc[ja+1][3] + a1h.y + b1h.y)*at.w;
                if (hh == 0) { p0h0 += c0; p1h0 += c1; }
                else         { p0h1 += c0; p1h1 += c1; }
            }
        }
        #pragma unroll
        for (int off = 1; off <= 2; off <<= 1) {
            p0h0 += __shfl_xor_sync(0xffffffffu, p0h0, off);
            p0h1 += __shfl_xor_sync(0xffffffffu, p0h1, off);
            p1h0 += __shfl_xor_sync(0xffffffffu, p1h0, off);
            p1h1 += __shfl_xor_sync(0xffffffffu, p1h1, off);
        }
        if (q == 0) {
            if (e0 + r0l < ETOT) {
                g_logits[(size_t)(e0 + r0l)*HEADS + half*2 + 0] = __expf(p0h0);
                g_logits[(size_t)(e0 + r0l)*HEADS + half*2 + 1] = __expf(p0h1);
            }
            if (e0 + r1l < ETOT) {
                g_logits[(size_t)(e0 + r1l)*HEADS + half*2 + 0] = __expf(p1h0);
                g_logits[(size_t)(e0 + r1l)*HEADS + half*2 + 1] = __expf(p1h1);
            }
        }
    }
}

// ---------------- node aggregation: single pass, normalize at end ------------
__global__ __launch_bounds__(256) void k_nodeagg(
    const float* __restrict__ bconv,
    const float* __restrict__ lnwP, const float* __restrict__ lnbP,
    const double* __restrict__ redP, double* __restrict__ redO)
{
    const int n    = (blockIdx.x*256 + threadIdx.x) >> 5;
    const int lane = threadIdx.x & 31;
    const int p0 = g_csr_ptr[n], p1 = g_csr_ptr[n+1];
    const int head = lane >> 3;
    float acc[8];
    #pragma unroll
    for (int j = 0; j < 8; j++) acc[j] = 0.f;
    float dsum = 0.f;
    int   s_nx   = g_csr_s[p0];
    float4 ex_nx = *(const float4*)(g_logits + (size_t)p0*HEADS);
    uint4  raw_nx = *(const uint4*)(g_xlrh + (size_t)s_nx*512 + lane*8);
    for (int idx = p0; idx < p1; idx++) {
        float4 ex = ex_nx;
        uint4 raw = raw_nx;
        if (idx + 1 < p1) {
            int s2 = g_csr_s[idx+1];
            ex_nx  = *(const float4*)(g_logits + (size_t)(idx+1)*HEADS);
            raw_nx = *(const uint4*)(g_xlrh + (size_t)s2*512 + lane*8);
        }
        float w = sel4(ex, head);
        dsum += w;
        float2 f0 = __half22float2(*(__half2*)&raw.x);
        float2 f1 = __half22float2(*(__half2*)&raw.y);
        float2 f2 = __half22float2(*(__half2*)&raw.z);
        float2 f3 = __half22float2(*(__half2*)&raw.w);
        acc[0] += w*f0.x; acc[1] += w*f0.y; acc[2] += w*f1.x; acc[3] += w*f1.y;
        acc[4] += w*f2.x; acc[5] += w*f2.y; acc[6] += w*f3.x; acc[7] += w*f3.y;
    }
    const float ih = 1.f / (dsum + 1e-16f);
    float* ph = g_h + (size_t)n*HID + lane*8;
    float4 h0 = __ldcs((const float4*)ph);
    float4 h1 = __ldcs((const float4*)(ph+4));
    float4 b0 = *(const float4*)(bconv + lane*8);
    float4 b1 = *(const float4*)(bconv + lane*8 + 4);
    float hv[8] = {h0.x,h0.y,h0.z,h0.w,h1.x,h1.y,h1.z,h1.w};
    float bv[8] = {b0.x,b0.y,b0.z,b0.w,b1.x,b1.y,b1.z,b1.w};
    if (lnwP) {
        double mu, rs;
        ln_params(redP, &mu, &rs);
        float4 w0 = *(const float4*)(lnwP + lane*8);
        float4 w1 = *(const float4*)(lnwP + lane*8 + 4);
        float4 l0 = *(const float4*)(lnbP + lane*8);
        float4 l1 = *(const float4*)(lnbP + lane*8 + 4);
        float wv[8] = {w0.x,w0.y,w0.z,w0.w,w1.x,w1.y,w1.z,w1.w};
        float lv[8] = {l0.x,l0.y,l0.z,l0.w,l1.x,l1.y,l1.z,l1.w};
        #pragma unroll
        for (int j = 0; j < 8; j++) {
            float sc = (float)rs * wv[j];
            hv[j] = hv[j]*sc + (lv[j] - (float)mu*sc);
        }
    }
    float s_ = 0.f, q_ = 0.f;
    float out8[8];
    #pragma unroll
    for (int j = 0; j < 8; j++) {
        float v  = acc[j]*ih + bv[j];
        float el = v > 0.f ? v : (__expf(v) - 1.f);
        float t  = hv[j] + el;
        out8[j] = t; s_ += t; q_ += t*t;
    }
    __stcs((float4*)ph,     make_float4(out8[0],out8[1],out8[2],out8[3]));
    __stcs((float4*)(ph+4), make_float4(out8[4],out8[5],out8[6],out8[7]));
    #pragma unroll
    for (int off = 16; off; off >>= 1) {
        s_ += __shfl_down_sync(0xffffffffu, s_, off);
        q_ += __shfl_down_sync(0xffffffffu, q_, off);
    }
    __shared__ float ss[8], sq[8];
    int w = threadIdx.x >> 5;
    if (lane == 0) { ss[w] = s_; sq[w] = q_; }
    __syncthreads();
    if (threadIdx.x == 0) {
        float S = 0.f, Q = 0.f;
        #pragma unroll
        for (int i = 0; i < 8; i++) { S += ss[i]; Q += sq[i]; }
        atomicAdd(&redO[0], (double)S);
        atomicAdd(&redO[1], (double)Q);
    }
}

// ---------------- launcher ---------------------------------------------------
extern "C" void kernel_launch(void* const* d_in, const int* in_sizes, int n_in,
                              void* d_out, int out_size)
{
    const float* x     = (const float*)d_in[0];
    const int*   ei    = (const int*)  d_in[1];
    const float* ea    = (const float*)d_in[2];
    const float* w_in  = (const float*)d_in[3];
    const float* b_in  = (const float*)d_in[4];
    const float* wl    = (const float*)d_in[5];
    const float* wr    = (const float*)d_in[6];
    const float* we    = (const float*)d_in[7];
    const float* att   = (const float*)d_in[8];
    const float* bconv = (const float*)d_in[9];
    const float* lnw   = (const float*)d_in[10];
    const float* lnb   = (const float*)d_in[11];
    const float* wout  = (const float*)d_in[12];
    const float* bout  = (const float*)d_in[13];
    float* out = (float*)d_out;
    const int* srcA = ei;
    const int* dstA = ei + NE;

    float *p_h, *p_winT, *p_wcatT, *p_woutT;
    __half* p_xlrh;
    int* p_degi;
    double* p_red;
    cudaGetSymbolAddress((void**)&p_h,     g_h);
    cudaGetSymbolAddress((void**)&p_xlrh,  g_xlrh);
    cudaGetSymbolAddress((void**)&p_degi,  g_degi);
    cudaGetSymbolAddress((void**)&p_winT,  g_winT);
    cudaGetSymbolAddress((void**)&p_wcatT, g_wcatT);
    cudaGetSymbolAddress((void**)&p_woutT, g_woutT);
    cudaGetSymbolAddress((void**)&p_red,   g_redL);
    double* redL0 = p_red;
    double* redL1 = p_red + 2;

    dim3 gIn (HID/128, (N_NODES + 127)/128);
    dim3 gXlr(512/128, (N_NODES + 127)/128);

    k_transpose<<<dim3(HID/32, DIN/32), 256>>>(w_in, p_winT, DIN, HID);
    tgemm<<<gIn, 256>>>(x, p_winT, b_in, p_h, nullptr,
                        nullptr, nullptr, nullptr, N_NODES, DIN, HID, 1);
    k_transcat<<<dim3(8, 8, 2), 256>>>(wl, wr);
    tgemm<<<gXlr, 256>>>(p_h, p_wcatT, nullptr, nullptr, p_xlrh,
                         nullptr, nullptr, nullptr, N_NODES, HID, 512, 0);

    k_zero_i<<<(N_NODES + 511)/512, 512>>>(p_degi, N_NODES);
    k_degc<<<(NE + 255)/256, 256>>>(dstA);
    k_scan<<<1, 1024>>>();
    k_scatter<<<(ETOT + 255)/256, 256>>>(srcA, dstA);
    k_eafuse<<<N_NODES/8, 256>>>(ea);
    k_transpose<<<dim3(HID/32, HID/32), 256>>>(wout, p_woutT, HID, HID);

    // ---- layer 0 ----
    k_weT<<<(HID*EDIM + 255)/256, 256>>>(we);
    k_eplogits<<<(ETOT + 127)/128, 256>>>(att);
    k_nodeagg<<<N_NODES/8, 256>>>(bconv, nullptr, nullptr, nullptr, redL0);

    // ---- layer 1 ----
    k_transcat<<<dim3(8, 8, 2), 256>>>(wl + (size_t)HID*HID, wr + (size_t)HID*HID);
    tgemm<<<gXlr, 256>>>(p_h, p_wcatT, nullptr, nullptr, p_xlrh,
                         lnw, lnb, redL0, N_NODES, HID, 512, 0);
    k_weT<<<(HID*EDIM + 255)/256, 256>>>(we + (size_t)EDIM*HID);
    k_eplogits<<<(ETOT + 127)/128, 256>>>(att + (size_t)HEADS*CDIM);
    k_nodeagg<<<N_NODES/8, 256>>>(bconv + HID, lnw, lnb, redL0, redL1);

    // ---- output GEMM applies layer-1 LN on the fly ----
    tgemm<<<gIn, 256>>>(p_h, p_woutT, bout, out, nullptr,
                        lnw + HID, lnb + HID, redL1, N_NODES, HID, HID, 0);
}

// round 16
// speedup vs baseline: 2.7157x; 1.0683x over previous
#include <cuda_runtime.h>
#include <cuda_fp16.h>
#include <math.h>
#include <stdint.h>

#define N_NODES 50000
#define NE      800000
#define ETOT    850000
#define DIN     384
#define HID     256
#define HEADS   4
#define CDIM    64
#define EDIM    32
#define NLAYER  2
#define SLOPE   0.2f
#define TOT_H   (N_NODES*HID)

// ---------------- scratch ----------------------------------------------------
__device__ float    g_h   [(size_t)N_NODES*HID];
__device__ __half   g_xlrh[(size_t)N_NODES*512];
__device__ int      g_degi[N_NODES];
__device__ float    g_logits[(size_t)ETOT*HEADS];   // holds exp(logit)
__device__ int      g_csr_ptr[N_NODES+1];
__device__ int      g_cursor [N_NODES];
__device__ int      g_csr_e [ETOT];
__device__ int      g_csr_s [ETOT];
__device__ int      g_csr_d [ETOT];
__device__ __half   g_each [(size_t)ETOT*EDIM];
__device__ __half   g_winT [(size_t)HID*DIN];    // [256][384] fp16
__device__ __half   g_wcatT[(size_t)512*HID];    // [512][256] fp16
__device__ float    g_weT  [(size_t)HID*EDIM];   // tf32 for eplogits (permuted)
__device__ __half   g_woutT[(size_t)HID*HID];    // [256][256] fp16
__device__ double   g_redL[2][2];

// ---------------- helpers ----------------------------------------------------
__device__ __forceinline__ float lrelu(float x){ return x > 0.f ? x : SLOPE*x; }
__device__ __forceinline__ float sel4(float4 v, int h){
    return h==0 ? v.x : (h==1 ? v.y : (h==2 ? v.z : v.w));
}
__device__ __forceinline__ uint32_t f2tf(float f){
    uint32_t u; asm("cvt.rna.tf32.f32 %0, %1;" : "=r"(u) : "f"(f)); return u;
}
__device__ __forceinline__ float tfF(float f){ return __uint_as_float(f2tf(f)); }
__device__ __forceinline__ uint32_t sptr(const void* p){
    return (uint32_t)__cvta_generic_to_shared(p);
}
__device__ __forceinline__ void mma8(float* c, const uint4& a, uint32_t b0, uint32_t b1){
    asm volatile("mma.sync.aligned.m16n8k8.row.col.f32.tf32.tf32.f32 "
        "{%0,%1,%2,%3}, {%4,%5,%6,%7}, {%8,%9}, {%0,%1,%2,%3};"
        : "+f"(c[0]), "+f"(c[1]), "+f"(c[2]), "+f"(c[3])
        : "r"(a.x), "r"(a.y), "r"(a.z), "r"(a.w), "r"(b0), "r"(b1));
}
__device__ __forceinline__ void mmaH(float* c, const uint4& a, uint32_t b0, uint32_t b1){
    asm volatile("mma.sync.aligned.m16n8k16.row.col.f32.f16.f16.f32 "
        "{%0,%1,%2,%3}, {%4,%5,%6,%7}, {%8,%9}, {%0,%1,%2,%3};"
        : "+f"(c[0]), "+f"(c[1]), "+f"(c[2]), "+f"(c[3])
        : "r"(a.x), "r"(a.y), "r"(a.z), "r"(a.w), "r"(b0), "r"(b1));
}
#define LDSM4(d, addr) \
    asm volatile("ldmatrix.sync.aligned.m8n8.x4.shared.b16 {%0,%1,%2,%3}, [%4];" \
        : "=r"((d).x), "=r"((d).y), "=r"((d).z), "=r"((d).w) : "r"(addr))

__device__ __forceinline__ void ln_params(const double* red, double* mu_o, double* rs_o){
    double M  = (double)TOT_H;
    double mu = red[0] / M;
    double var = red[1] / M - mu*mu;
    if (var < 0.0) var = 0.0;
    *mu_o = mu;
    *rs_o = 1.0 / (sqrt(var) + 1e-5);
}

// ---------------- setup ------------------------------------------------------
__global__ void k_zero_i(int* p, int n){
    int i = blockIdx.x*blockDim.x + threadIdx.x;
    if (i < n) p[i] = 0;
}
__global__ void k_degc(const int* __restrict__ dst){
    int t = blockIdx.x*blockDim.x + threadIdx.x;
    if (t < NE) atomicAdd(&g_degi[dst[t]], 1);
}

__global__ void k_scan(){
    __shared__ int wsum[32];
    int tid = threadIdx.x, lane = tid & 31, w = tid >> 5;
    int carry = 0;
    if (tid == 0) {
        g_csr_ptr[0] = 0;
        g_redL[0][0] = 0.0; g_redL[0][1] = 0.0;
        g_redL[1][0] = 0.0; g_redL[1][1] = 0.0;
    }
    for (int base = 0; base < N_NODES; base += 1024) {
        int i = base + tid;
        int v = (i < N_NODES) ? (g_degi[i] + 1) : 0;
        int x = v;
        #pragma unroll
        for (int off = 1; off < 32; off <<= 1) {
            int nb = __shfl_up_sync(0xffffffffu, x, off);
            if (lane >= off) x += nb;
        }
        if (lane == 31) wsum[w] = x;
        __syncthreads();
        if (w == 0) {
            int y = wsum[lane];
            #pragma unroll
            for (int off = 1; off < 32; off <<= 1) {
                int nb = __shfl_up_sync(0xffffffffu, y, off);
                if (lane >= off) y += nb;
            }
            wsum[lane] = y;
        }
        __syncthreads();
        int add  = (w > 0) ? wsum[w-1] : 0;
        int incl = carry + add + x;
        if (i < N_NODES) { g_csr_ptr[i+1] = incl; g_cursor[i] = incl - v; }
        carry += wsum[31];
        __syncthreads();
    }
}
__global__ void k_scatter(const int* __restrict__ src, const int* __restrict__ dst){
    int t = blockIdx.x*blockDim.x + threadIdx.x;
    if (t >= ETOT) return;
    int s, d;
    if (t < NE) { s = src[t]; d = dst[t]; } else { s = t - NE; d = s; }
    int pos = atomicAdd(&g_cursor[d], 1);
    g_csr_e[pos] = t;
    g_csr_s[pos] = s;
    g_csr_d[pos] = d;
}

__global__ __launch_bounds__(256) void k_eafuse(const float* __restrict__ ea){
    int n = (blockIdx.x*256 + threadIdx.x) >> 5;
    int lane = threadIdx.x & 31;
    int p0 = g_csr_ptr[n], p1 = g_csr_ptr[n+1];
    float sum = 0.f; int deg = 0; int selfpos = p0;
    int e_next = g_csr_e[p0];
    for (int pos = p0; pos < p1; pos++) {
        int e = e_next;
        if (pos + 1 < p1) e_next = g_csr_e[pos+1];
        if (e < NE) {
            float v = __ldcs(ea + (size_t)e*EDIM + lane);
            sum += v; deg++;
            g_each[(size_t)pos*EDIM + lane] = __float2half_rn(v);
        } else selfpos = pos;
    }
    float mean = sum / fmaxf((float)deg, 1.f);
    g_each[(size_t)selfpos*EDIM + lane] = __float2half_rn(mean);
}

// ---------------- weight prep (fp16 outputs for tgemm) -----------------------
__global__ void k_transpose(const float* __restrict__ in, __half* __restrict__ out,
                            int K, int N){
    __shared__ float t[32][33];
    int kb = blockIdx.y*32, nb = blockIdx.x*32;
    int tx = threadIdx.x & 31, ty = threadIdx.x >> 5;
    #pragma unroll
    for (int i = ty; i < 32; i += 8)
        t[i][tx] = in[(size_t)(kb+i)*N + nb + tx];
    __syncthreads();
    #pragma unroll
    for (int i = ty; i < 32; i += 8)
        out[(size_t)(nb+i)*K + kb + tx] = __float2half_rn(t[tx][i]);
}
__global__ void k_transcat(const float* __restrict__ wl, const float* __restrict__ wr){
    __shared__ float t[32][33];
    const float* in = blockIdx.z ? wr : wl;
    __half* out = g_wcatT + (size_t)blockIdx.z*HID*HID;
    int kb = blockIdx.y*32, nb = blockIdx.x*32;
    int tx = threadIdx.x & 31, ty = threadIdx.x >> 5;
    #pragma unroll
    for (int i = ty; i < 32; i += 8)
        t[i][tx] = in[(size_t)(kb+i)*HID + nb + tx];
    __syncthreads();
    #pragma unroll
    for (int i = ty; i < 32; i += 8)
        out[(size_t)(nb+i)*HID + kb + tx] = __float2half_rn(t[tx][i]);
}
// weT (tf32, permuted) for eplogits — unchanged
__global__ void k_weT(const float* __restrict__ we){
    int t = blockIdx.x*blockDim.x + threadIdx.x;
    if (t >= HID*EDIM) return;
    int n_f = t >> 5, k = t & 31;
    int half = n_f >> 7, rem = n_f & 127;
    int hh  = rem >> 6;
    int jm  = (rem >> 3) & 7;
    int low = rem & 7, qq = low >> 1, pair = low & 1;
    int tt = jm >> 1, p = jm & 1;
    int a = half*128 + hh*64 + tt*16 + qq*4 + p*2 + pair;
    g_weT[t] = tfF(we[(size_t)k*HID + a]);
}

// ---------------- FP16 m16n8k16 GEMM, optional fused LN on A -----------------
// A [M][K] fp32; Bt [N][K] fp16. BK=32 k-elements per stage, double-buffered.
#define HPAD 40
__global__ __launch_bounds__(256) void tgemm(
    const float* __restrict__ A, const __half* __restrict__ Bt,
    const float* __restrict__ bias, float* __restrict__ C,
    __half* __restrict__ Ch,
    const float* __restrict__ lnw, const float* __restrict__ lnb,
    const double* __restrict__ red,
    int M, int K, int Nn, int act)
{
    __shared__ __half As[2][128*HPAD];
    __shared__ __half Bs[2][128*HPAD];
    __shared__ float sTab[384], bTab[384];
    const int tid = threadIdx.x, lane = tid & 31, wid = tid >> 5;
    const int wm = (wid & 1)*64, wn = (wid >> 1)*32;
    const int cRow = blockIdx.y*128, cCol = blockIdx.x*128;
    const int r0 = tid >> 1, seg = (tid & 1)*16;   // row 0..127, 16 k-elems each
    const bool doNorm = (lnw != nullptr);

    if (doNorm) {
        double mu, rs;
        ln_params(red, &mu, &rs);
        for (int k = tid; k < K; k += 256) {
            float sc = (float)rs * lnw[k];
            sTab[k] = sc;
            bTab[k] = lnb[k] - (float)mu * sc;
        }
    }
    __syncthreads();

    // fragment offsets (bytes)
    const int aoff = (((lane & 15))*HPAD + (lane >> 4)*8)*2;
    const int boff = ((((lane & 7) + ((lane >> 4) << 3)))*HPAD + ((lane >> 3) & 1)*8)*2;

    float acc[4][4][4];
    #pragma unroll
    for (int i = 0; i < 4; i++)
        #pragma unroll
        for (int j = 0; j < 4; j++)
            #pragma unroll
            for (int v = 0; v < 4; v++) acc[i][j][v] = 0.f;

    float4 aF[4];
    uint4  bF[2];
#define LDG_TILE(kt) { \
    int gr = cRow + r0; \
    if (gr < M) { \
        const float* p = A + (size_t)gr*K + (kt) + seg; \
        aF[0] = *(const float4*)(p); aF[1] = *(const float4*)(p+4); \
        aF[2] = *(const float4*)(p+8); aF[3] = *(const float4*)(p+12); \
    } else { \
        aF[0]=aF[1]=aF[2]=aF[3]=make_float4(0,0,0,0); \
    } \
    if (doNorm) { \
        _Pragma("unroll") \
        for (int u = 0; u < 4; u++) { \
            float4 sc = *(const float4*)(sTab + (kt) + seg + u*4); \
            float4 bs = *(const float4*)(bTab + (kt) + seg + u*4); \
            aF[u].x = aF[u].x*sc.x + bs.x; aF[u].y = aF[u].y*sc.y + bs.y; \
            aF[u].z = aF[u].z*sc.z + bs.z; aF[u].w = aF[u].w*sc.w + bs.w; \
        } \
    } \
    const uint4* pb = (const uint4*)(Bt + (size_t)(cCol + r0)*K + (kt) + seg); \
    bF[0] = pb[0]; bF[1] = pb[1]; }
#define STS_TILE(b) { \
    uint4 h0, h1; \
    ((__half2*)&h0)[0] = __floats2half2_rn(aF[0].x, aF[0].y); \
    ((__half2*)&h0)[1] = __floats2half2_rn(aF[0].z, aF[0].w); \
    ((__half2*)&h0)[2] = __floats2half2_rn(aF[1].x, aF[1].y); \
    ((__half2*)&h0)[3] = __floats2half2_rn(aF[1].z, aF[1].w); \
    ((__half2*)&h1)[0] = __floats2half2_rn(aF[2].x, aF[2].y); \
    ((__half2*)&h1)[1] = __floats2half2_rn(aF[2].z, aF[2].w); \
    ((__half2*)&h1)[2] = __floats2half2_rn(aF[3].x, aF[3].y); \
    ((__half2*)&h1)[3] = __floats2half2_rn(aF[3].z, aF[3].w); \
    uint4* pa = (uint4*)(&As[b][r0*HPAD + seg]); \
    pa[0] = h0; pa[1] = h1; \
    uint4* pb2 = (uint4*)(&Bs[b][r0*HPAD + seg]); \
    pb2[0] = bF[0]; pb2[1] = bF[1]; }
#define COMPUTE(b) { \
    uint32_t ab = sptr(&As[b][0]) + wm*HPAD*2 + aoff; \
    uint32_t bb = sptr(&Bs[b][0]) + wn*HPAD*2 + boff; \
    _Pragma("unroll") \
    for (int ks = 0; ks < 2; ks++) { \
        uint4 af0, af1, af2, af3, bf0, bf1; \
        LDSM4(af0, ab + ks*32); \
        LDSM4(af1, ab + 16*HPAD*2 + ks*32); \
        LDSM4(af2, ab + 32*HPAD*2 + ks*32); \
        LDSM4(af3, ab + 48*HPAD*2 + ks*32); \
        LDSM4(bf0, bb + ks*32); \
        LDSM4(bf1, bb + 16*HPAD*2 + ks*32); \
        mmaH(acc[0][0], af0, bf0.x, bf0.y); mmaH(acc[0][1], af0, bf0.z, bf0.w); \
        mmaH(acc[0][2], af0, bf1.x, bf1.y); mmaH(acc[0][3], af0, bf1.z, bf1.w); \
        mmaH(acc[1][0], af1, bf0.x, bf0.y); mmaH(acc[1][1], af1, bf0.z, bf0.w); \
        mmaH(acc[1][2], af1, bf1.x, bf1.y); mmaH(acc[1][3], af1, bf1.z, bf1.w); \
        mmaH(acc[2][0], af2, bf0.x, bf0.y); mmaH(acc[2][1], af2, bf0.z, bf0.w); \
        mmaH(acc[2][2], af2, bf1.x, bf1.y); mmaH(acc[2][3], af2, bf1.z, bf1.w); \
        mmaH(acc[3][0], af3, bf0.x, bf0.y); mmaH(acc[3][1], af3, bf0.z, bf0.w); \
        mmaH(acc[3][2], af3, bf1.x, bf1.y); mmaH(acc[3][3], af3, bf1.z, bf1.w); \
    } }

    LDG_TILE(0);
    STS_TILE(0);
    __syncthreads();
    int buf = 0;
    for (int kt = 32; kt < K; kt += 32) {
        LDG_TILE(kt);
        COMPUTE(buf);
        STS_TILE(buf ^ 1);
        __syncthreads();
        buf ^= 1;
    }
    COMPUTE(buf);

    const int g = lane >> 2, q = lane & 3;
    #pragma unroll
    for (int mf = 0; mf < 4; mf++) {
        int rA = cRow + wm + mf*16 + g;
        #pragma unroll
        for (int nf = 0; nf < 4; nf++) {
            int col = cCol + wn + nf*8 + 2*q;
            float bx = 0.f, by = 0.f;
            if (bias) { float2 bb = *(const float2*)(bias + col); bx = bb.x; by = bb.y; }
            float v0 = acc[mf][nf][0] + bx, v1 = acc[mf][nf][1] + by;
            float v2 = acc[mf][nf][2] + bx, v3 = acc[mf][nf][3] + by;
            if (act == 1) {
                v0 = fmaxf(v0,0.f); v1 = fmaxf(v1,0.f);
                v2 = fmaxf(v2,0.f); v3 = fmaxf(v3,0.f);
            }
            if (Ch) {
                if (rA < M)
                    *(__half2*)(Ch + (size_t)rA*Nn + col) = __floats2half2_rn(v0, v1);
                if (rA+8 < M)
                    *(__half2*)(Ch + (size_t)(rA+8)*Nn + col) = __floats2half2_rn(v2, v3);
            } else {
                if (rA < M)     *(float2*)(C + (size_t)rA*Nn + col)     = make_float2(v0,v1);
                if (rA+8 < M)   *(float2*)(C + (size_t)(rA+8)*Nn + col) = make_float2(v2,v3);
            }
        }
    }
#undef LDG_TILE
#undef STS_TILE
#undef COMPUTE
}

// ---------------- fused ep-GEMM + logits (tf32, unchanged); stores exp -------
#define EPAD 36
__global__ __launch_bounds__(256) void k_eplogits(const float* __restrict__ attL)
{
    __shared__ float As[128*EPAD];
    __shared__ float Bs[256*EPAD];
    __shared__ int s_src[128], s_dst[128];
    const int tid = threadIdx.x, lane = tid & 31, wid = tid >> 5;
    const int q = lane & 3, g = lane >> 2;
    const int e0 = blockIdx.x * 128;

    for (int i = tid; i < 128; i += 256) {
        int pos = e0 + i, s = 0, d = 0;
        if (pos < ETOT) { s = g_csr_s[pos]; d = g_csr_d[pos]; }
        s_src[i] = s; s_dst[i] = d;
    }
    #pragma unroll
    for (int i = 0; i < 2; i++) {
        int f = tid + i*256;
        int row = f >> 2, q4 = f & 3;
        int pos = e0 + row;
        uint4 raw = make_uint4(0,0,0,0);
        if (pos < ETOT)
            raw = __ldcs((const uint4*)(g_each + (size_t)pos*EDIM + q4*8));
        float2 f0 = __half22float2(*(__half2*)&raw.x);
        float2 f1 = __half22float2(*(__half2*)&raw.y);
        float2 f2 = __half22float2(*(__half2*)&raw.z);
        float2 f3 = __half22float2(*(__half2*)&raw.w);
        *(float4*)(&As[row*EPAD + q4*8])     = make_float4(f0.x,f0.y,f1.x,f1.y);
        *(float4*)(&As[row*EPAD + q4*8 + 4]) = make_float4(f2.x,f2.y,f3.x,f3.y);
    }
    #pragma unroll
    for (int i = 0; i < 8; i++) {
        int f = tid + i*256;
        int row = f >> 3, q8 = f & 7;
        *(float4*)(&Bs[row*EPAD + q8*4]) =
            *(const float4*)(g_weT + (size_t)row*EDIM + q8*4);
    }
    __syncthreads();

    const int aoff = ((wid*16 + (lane & 15))*EPAD + ((lane >> 4) << 2))*4;
    const int boff = (((lane & 15))*EPAD + ((lane >> 4) << 2))*4;
    const int r0l = wid*16 + g, r1l = r0l + 8;
    const int s0 = s_src[r0l], d0 = s_dst[r0l];
    const int s1 = s_src[r1l], d1 = s_dst[r1l];
    const uint32_t ab = sptr(&As[0]) + aoff;
    const uint32_t bb = sptr(&Bs[0]) + boff;

    #pragma unroll
    for (int half = 0; half < 2; half++) {
        float acc[16][4];
        #pragma unroll
        for (int j = 0; j < 16; j++)
            #pragma unroll
            for (int v = 0; v < 4; v++) acc[j][v] = 0.f;
        uint32_t bbh = bb + half*(128*EPAD*4);
        #pragma unroll
        for (int ks = 0; ks < 4; ks++) {
            uint4 a;
            LDSM4(a, ab + (ks*8)*4);
            #pragma unroll
            for (int nt = 0; nt < 8; nt++) {
                uint4 b;
                LDSM4(b, bbh + (nt*16*EPAD + ks*8)*4);
                mma8(acc[nt*2+0], a, b.x, b.z);
                mma8(acc[nt*2+1], a, b.y, b.w);
            }
        }
        float p0h0 = 0.f, p0h1 = 0.f, p1h0 = 0.f, p1h1 = 0.f;
        #pragma unroll
        for (int hh = 0; hh < 2; hh++) {
            #pragma unroll
            for (int t = 0; t < 4; t++) {
                int cb = half*128 + hh*64 + t*16 + q*4;
                float4 at = *(const float4*)(attL + cb);
                uint2 ra0 = *(const uint2*)(g_xlrh + (size_t)s0*512 + cb);
                uint2 rb0 = *(const uint2*)(g_xlrh + (size_t)d0*512 + 256 + cb);
                uint2 ra1 = *(const uint2*)(g_xlrh + (size_t)s1*512 + cb);
                uint2 rb1 = *(const uint2*)(g_xlrh + (size_t)d1*512 + 256 + cb);
                float2 a0l = __half22float2(*(__half2*)&ra0.x);
                float2 a0h = __half22float2(*(__half2*)&ra0.y);
                float2 b0l = __half22float2(*(__half2*)&rb0.x);
                float2 b0h = __half22float2(*(__half2*)&rb0.y);
                float2 a1l = __half22float2(*(__half2*)&ra1.x);
                float2 a1h = __half22float2(*(__half2*)&ra1.y);
                float2 b1l = __half22float2(*(__half2*)&rb1.x);
                float2 b1h = __half22float2(*(__half2*)&rb1.y);
                int ja = hh*8 + 2*t;
                float c0 = lrelu(acc[ja][0]   + a0l.x + b0l.x)*at.x
                         + lrelu(acc[ja][1]   + a0l.y + b0l.y)*at.y
                         + lrelu(acc[ja+1][0] + a0h.x + b0h.x)*at.z
                         + lrelu(acc[ja+1][1] + a0h.y + b0h.y)*at.w;
                float c1 = lrelu(acc[ja][2]   + a1l.x + b1l.x)*at.x
                         + lrelu(acc[ja][3]   + a1l.y + b1l.y)*at.y
                         + lrelu(acc[ja+1][2] + a1h.x + b1h.x)*at.z
                         + lrelu(acc[ja+1][3] + a1h.y + b1h.y)*at.w;
                if (hh == 0) { p0h0 += c0; p1h0 += c1; }
                else         { p0h1 += c0; p1h1 += c1; }
            }
        }
        #pragma unroll
        for (int off = 1; off <= 2; off <<= 1) {
            p0h0 += __shfl_xor_sync(0xffffffffu, p0h0, off);
            p0h1 += __shfl_xor_sync(0xffffffffu, p0h1, off);
            p1h0 += __shfl_xor_sync(0xffffffffu, p1h0, off);
            p1h1 += __shfl_xor_sync(0xffffffffu, p1h1, off);
        }
        if (q == 0) {
            if (e0 + r0l < ETOT) {
                g_logits[(size_t)(e0 + r0l)*HEADS + half*2 + 0] = __expf(p0h0);
                g_logits[(size_t)(e0 + r0l)*HEADS + half*2 + 1] = __expf(p0h1);
            }
            if (e0 + r1l < ETOT) {
                g_logits[(size_t)(e0 + r1l)*HEADS + half*2 + 0] = __expf(p1h0);
                g_logits[(size_t)(e0 + r1l)*HEADS + half*2 + 1] = __expf(p1h1);
            }
        }
    }
}

// ---------------- node aggregation: single pass ------------------------------
__global__ __launch_bounds__(256) void k_nodeagg(
    const float* __restrict__ bconv,
    const float* __restrict__ lnwP, const float* __restrict__ lnbP,
    const double* __restrict__ redP, double* __restrict__ redO)
{
    const int n    = (blockIdx.x*256 + threadIdx.x) >> 5;
    const int lane = threadIdx.x & 31;
    const int p0 = g_csr_ptr[n], p1 = g_csr_ptr[n+1];
    const int head = lane >> 3;
    float acc[8];
    #pragma unroll
    for (int j = 0; j < 8; j++) acc[j] = 0.f;
    float dsum = 0.f;
    int   s_nx   = g_csr_s[p0];
    float4 ex_nx = *(const float4*)(g_logits + (size_t)p0*HEADS);
    uint4  raw_nx = *(const uint4*)(g_xlrh + (size_t)s_nx*512 + lane*8);
    for (int idx = p0; idx < p1; idx++) {
        float4 ex = ex_nx;
        uint4 raw = raw_nx;
        if (idx + 1 < p1) {
            int s2 = g_csr_s[idx+1];
            ex_nx  = *(const float4*)(g_logits + (size_t)(idx+1)*HEADS);
            raw_nx = *(const uint4*)(g_xlrh + (size_t)s2*512 + lane*8);
        }
        float w = sel4(ex, head);
        dsum += w;
        float2 f0 = __half22float2(*(__half2*)&raw.x);
        float2 f1 = __half22float2(*(__half2*)&raw.y);
        float2 f2 = __half22float2(*(__half2*)&raw.z);
        float2 f3 = __half22float2(*(__half2*)&raw.w);
        acc[0] += w*f0.x; acc[1] += w*f0.y; acc[2] += w*f1.x; acc[3] += w*f1.y;
        acc[4] += w*f2.x; acc[5] += w*f2.y; acc[6] += w*f3.x; acc[7] += w*f3.y;
    }
    const float ih = 1.f / (dsum + 1e-16f);
    float* ph = g_h + (size_t)n*HID + lane*8;
    float4 h0 = __ldcs((const float4*)ph);
    float4 h1 = __ldcs((const float4*)(ph+4));
    float4 b0 = *(const float4*)(bconv + lane*8);
    float4 b1 = *(const float4*)(bconv + lane*8 + 4);
    float hv[8] = {h0.x,h0.y,h0.z,h0.w,h1.x,h1.y,h1.z,h1.w};
    float bv[8] = {b0.x,b0.y,b0.z,b0.w,b1.x,b1.y,b1.z,b1.w};
    if (lnwP) {
        double mu, rs;
        ln_params(redP, &mu, &rs);
        float4 w0 = *(const float4*)(lnwP + lane*8);
        float4 w1 = *(const float4*)(lnwP + lane*8 + 4);
        float4 l0 = *(const float4*)(lnbP + lane*8);
        float4 l1 = *(const float4*)(lnbP + lane*8 + 4);
        float wv[8] = {w0.x,w0.y,w0.z,w0.w,w1.x,w1.y,w1.z,w1.w};
        float lv[8] = {l0.x,l0.y,l0.z,l0.w,l1.x,l1.y,l1.z,l1.w};
        #pragma unroll
        for (int j = 0; j < 8; j++) {
            float sc = (float)rs * wv[j];
            hv[j] = hv[j]*sc + (lv[j] - (float)mu*sc);
        }
    }
    float s_ = 0.f, q_ = 0.f;
    float out8[8];
    #pragma unroll
    for (int j = 0; j < 8; j++) {
        float v  = acc[j]*ih + bv[j];
        float el = v > 0.f ? v : (__expf(v) - 1.f);
        float t  = hv[j] + el;
        out8[j] = t; s_ += t; q_ += t*t;
    }
    __stcs((float4*)ph,     make_float4(out8[0],out8[1],out8[2],out8[3]));
    __stcs((float4*)(ph+4), make_float4(out8[4],out8[5],out8[6],out8[7]));
    #pragma unroll
    for (int off = 16; off; off >>= 1) {
        s_ += __shfl_down_sync(0xffffffffu, s_, off);
        q_ += __shfl_down_sync(0xffffffffu, q_, off);
    }
    __shared__ float ss[8], sq[8];
    int w = threadIdx.x >> 5;
    if (lane == 0) { ss[w] = s_; sq[w] = q_; }
    __syncthreads();
    if (threadIdx.x == 0) {
        float S = 0.f, Q = 0.f;
        #pragma unroll
        for (int i = 0; i < 8; i++) { S += ss[i]; Q += sq[i]; }
        atomicAdd(&redO[0], (double)S);
        atomicAdd(&redO[1], (double)Q);
    }
}

// ---------------- launcher ---------------------------------------------------
extern "C" void kernel_launch(void* const* d_in, const int* in_sizes, int n_in,
                              void* d_out, int out_size)
{
    const float* x     = (const float*)d_in[0];
    const int*   ei    = (const int*)  d_in[1];
    const float* ea    = (const float*)d_in[2];
    const float* w_in  = (const float*)d_in[3];
    const float* b_in  = (const float*)d_in[4];
    const float* wl    = (const float*)d_in[5];
    const float* wr    = (const float*)d_in[6];
    const float* we    = (const float*)d_in[7];
    const float* att   = (const float*)d_in[8];
    const float* bconv = (const float*)d_in[9];
    const float* lnw   = (const float*)d_in[10];
    const float* lnb   = (const float*)d_in[11];
    const float* wout  = (const float*)d_in[12];
    const float* bout  = (const float*)d_in[13];
    float* out = (float*)d_out;
    const int* srcA = ei;
    const int* dstA = ei + NE;

    float *p_h;
    __half *p_xlrh, *p_winT, *p_wcatT, *p_woutT;
    int* p_degi;
    double* p_red;
    cudaGetSymbolAddress((void**)&p_h,     g_h);
    cudaGetSymbolAddress((void**)&p_xlrh,  g_xlrh);
    cudaGetSymbolAddress((void**)&p_degi,  g_degi);
    cudaGetSymbolAddress((void**)&p_winT,  g_winT);
    cudaGetSymbolAddress((void**)&p_wcatT, g_wcatT);
    cudaGetSymbolAddress((void**)&p_woutT, g_woutT);
    cudaGetSymbolAddress((void**)&p_red,   g_redL);
    double* redL0 = p_red;
    double* redL1 = p_red + 2;

    dim3 gIn (HID/128, (N_NODES + 127)/128);
    dim3 gXlr(512/128, (N_NODES + 127)/128);

    k_transpose<<<dim3(HID/32, DIN/32), 256>>>(w_in, p_winT, DIN, HID);
    tgemm<<<gIn, 256>>>(x, p_winT, b_in, p_h, nullptr,
                        nullptr, nullptr, nullptr, N_NODES, DIN, HID, 1);
    k_transcat<<<dim3(8, 8, 2), 256>>>(wl, wr);
    tgemm<<<gXlr, 256>>>(p_h, p_wcatT, nullptr, nullptr, p_xlrh,
                         nullptr, nullptr, nullptr, N_NODES, HID, 512, 0);

    k_zero_i<<<(N_NODES + 511)/512, 512>>>(p_degi, N_NODES);
    k_degc<<<(NE + 255)/256, 256>>>(dstA);
    k_scan<<<1, 1024>>>();
    k_scatter<<<(ETOT + 255)/256, 256>>>(srcA, dstA);
    k_eafuse<<<N_NODES/8, 256>>>(ea);
    k_transpose<<<dim3(HID/32, HID/32), 256>>>(wout, p_woutT, HID, HID);

    // ---- layer 0 ----
    k_weT<<<(HID*EDIM + 255)/256, 256>>>(we);
    k_eplogits<<<(ETOT + 127)/128, 256>>>(att);
    k_nodeagg<<<N_NODES/8, 256>>>(bconv, nullptr, nullptr, nullptr, redL0);

    // ---- layer 1 ----
    k_transcat<<<dim3(8, 8, 2), 256>>>(wl + (size_t)HID*HID, wr + (size_t)HID*HID);
    tgemm<<<gXlr, 256>>>(p_h, p_wcatT, nullptr, nullptr, p_xlrh,
                         lnw, lnb, redL0, N_NODES, HID, 512, 0);
    k_weT<<<(HID*EDIM + 255)/256, 256>>>(we + (size_t)EDIM*HID);
    k_eplogits<<<(ETOT + 127)/128, 256>>>(att + (size_t)HEADS*CDIM);
    k_nodeagg<<<N_NODES/8, 256>>>(bconv + HID, lnw, lnb, redL0, redL1);

    // ---- output GEMM applies layer-1 LN ----
    tgemm<<<gIn, 256>>>(p_h, p_woutT, bout, out, nullptr,
                        lnw + HID, lnb + HID, redL1, N_NODES, HID, HID, 0);
}

// round 17
// speedup vs baseline: 2.8631x; 1.0543x over previous
#include <cuda_runtime.h>
#include <cuda_fp16.h>
#include <math.h>
#include <stdint.h>

#define N_NODES 50000
#define NE      800000
#define ETOT    850000
#define DIN     384
#define HID     256
#define HEADS   4
#define CDIM    64
#define EDIM    32
#define NLAYER  2
#define SLOPE   0.2f
#define TOT_H   (N_NODES*HID)

// ---------------- scratch ----------------------------------------------------
__device__ float    g_h   [(size_t)N_NODES*HID];
__device__ __half   g_xlrh[(size_t)N_NODES*512];
__device__ int      g_degi[N_NODES];
__device__ float    g_logits[(size_t)ETOT*HEADS];   // holds exp(logit)
__device__ int      g_csr_ptr[N_NODES+1];
__device__ int      g_cursor [N_NODES];
__device__ int      g_csr_e [ETOT];
__device__ int      g_csr_s [ETOT];
__device__ int      g_csr_d [ETOT];
__device__ __half   g_each [(size_t)ETOT*EDIM];
__device__ __half   g_winT [(size_t)HID*DIN];    // [256][384] fp16
__device__ __half   g_wcatT[(size_t)512*HID];    // [512][256] fp16
__device__ __half   g_weT  [(size_t)HID*EDIM];   // fp16, col-permuted, [n_f][32]
__device__ __half   g_woutT[(size_t)HID*HID];    // [256][256] fp16
__device__ double   g_redL[2][2];

// ---------------- helpers ----------------------------------------------------
__device__ __forceinline__ float lrelu(float x){ return x > 0.f ? x : SLOPE*x; }
__device__ __forceinline__ float sel4(float4 v, int h){
    return h==0 ? v.x : (h==1 ? v.y : (h==2 ? v.z : v.w));
}
__device__ __forceinline__ uint32_t sptr(const void* p){
    return (uint32_t)__cvta_generic_to_shared(p);
}
__device__ __forceinline__ void mmaH(float* c, const uint4& a, uint32_t b0, uint32_t b1){
    asm volatile("mma.sync.aligned.m16n8k16.row.col.f32.f16.f16.f32 "
        "{%0,%1,%2,%3}, {%4,%5,%6,%7}, {%8,%9}, {%0,%1,%2,%3};"
        : "+f"(c[0]), "+f"(c[1]), "+f"(c[2]), "+f"(c[3])
        : "r"(a.x), "r"(a.y), "r"(a.z), "r"(a.w), "r"(b0), "r"(b1));
}
#define LDSM4(d, addr) \
    asm volatile("ldmatrix.sync.aligned.m8n8.x4.shared.b16 {%0,%1,%2,%3}, [%4];" \
        : "=r"((d).x), "=r"((d).y), "=r"((d).z), "=r"((d).w) : "r"(addr))

__device__ __forceinline__ void ln_params(const double* red, double* mu_o, double* rs_o){
    double M  = (double)TOT_H;
    double mu = red[0] / M;
    double var = red[1] / M - mu*mu;
    if (var < 0.0) var = 0.0;
    *mu_o = mu;
    *rs_o = 1.0 / (sqrt(var) + 1e-5);
}

// ---------------- setup ------------------------------------------------------
__global__ void k_zero_i(int* p, int n){
    int i = blockIdx.x*blockDim.x + threadIdx.x;
    if (i < n) p[i] = 0;
}
__global__ void k_degc(const int* __restrict__ dst){
    int t = blockIdx.x*blockDim.x + threadIdx.x;
    if (t < NE) atomicAdd(&g_degi[dst[t]], 1);
}

__global__ void k_scan(){
    __shared__ int wsum[32];
    int tid = threadIdx.x, lane = tid & 31, w = tid >> 5;
    int carry = 0;
    if (tid == 0) {
        g_csr_ptr[0] = 0;
        g_redL[0][0] = 0.0; g_redL[0][1] = 0.0;
        g_redL[1][0] = 0.0; g_redL[1][1] = 0.0;
    }
    for (int base = 0; base < N_NODES; base += 1024) {
        int i = base + tid;
        int v = (i < N_NODES) ? (g_degi[i] + 1) : 0;
        int x = v;
        #pragma unroll
        for (int off = 1; off < 32; off <<= 1) {
            int nb = __shfl_up_sync(0xffffffffu, x, off);
            if (lane >= off) x += nb;
        }
        if (lane == 31) wsum[w] = x;
        __syncthreads();
        if (w == 0) {
            int y = wsum[lane];
            #pragma unroll
            for (int off = 1; off < 32; off <<= 1) {
                int nb = __shfl_up_sync(0xffffffffu, y, off);
                if (lane >= off) y += nb;
            }
            wsum[lane] = y;
        }
        __syncthreads();
        int add  = (w > 0) ? wsum[w-1] : 0;
        int incl = carry + add + x;
        if (i < N_NODES) { g_csr_ptr[i+1] = incl; g_cursor[i] = incl - v; }
        carry += wsum[31];
        __syncthreads();
    }
}
__global__ void k_scatter(const int* __restrict__ src, const int* __restrict__ dst){
    int t = blockIdx.x*blockDim.x + threadIdx.x;
    if (t >= ETOT) return;
    int s, d;
    if (t < NE) { s = src[t]; d = dst[t]; } else { s = t - NE; d = s; }
    int pos = atomicAdd(&g_cursor[d], 1);
    g_csr_e[pos] = t;
    g_csr_s[pos] = s;
    g_csr_d[pos] = d;
}

__global__ __launch_bounds__(256) void k_eafuse(const float* __restrict__ ea){
    int n = (blockIdx.x*256 + threadIdx.x) >> 5;
    int lane = threadIdx.x & 31;
    int p0 = g_csr_ptr[n], p1 = g_csr_ptr[n+1];
    float sum = 0.f; int deg = 0; int selfpos = p0;
    int e_next = g_csr_e[p0];
    for (int pos = p0; pos < p1; pos++) {
        int e = e_next;
        if (pos + 1 < p1) e_next = g_csr_e[pos+1];
        if (e < NE) {
            float v = __ldcs(ea + (size_t)e*EDIM + lane);
            sum += v; deg++;
            g_each[(size_t)pos*EDIM + lane] = __float2half_rn(v);
        } else selfpos = pos;
    }
    float mean = sum / fmaxf((float)deg, 1.f);
    g_each[(size_t)selfpos*EDIM + lane] = __float2half_rn(mean);
}

// ---------------- weight prep (fp16) -----------------------------------------
__global__ void k_transpose(const float* __restrict__ in, __half* __restrict__ out,
                            int K, int N){
    __shared__ float t[32][33];
    int kb = blockIdx.y*32, nb = blockIdx.x*32;
    int tx = threadIdx.x & 31, ty = threadIdx.x >> 5;
    #pragma unroll
    for (int i = ty; i < 32; i += 8)
        t[i][tx] = in[(size_t)(kb+i)*N + nb + tx];
    __syncthreads();
    #pragma unroll
    for (int i = ty; i < 32; i += 8)
        out[(size_t)(nb+i)*K + kb + tx] = __float2half_rn(t[tx][i]);
}
__global__ void k_transcat(const float* __restrict__ wl, const float* __restrict__ wr){
    __shared__ float t[32][33];
    const float* in = blockIdx.z ? wr : wl;
    __half* out = g_wcatT + (size_t)blockIdx.z*HID*HID;
    int kb = blockIdx.y*32, nb = blockIdx.x*32;
    int tx = threadIdx.x & 31, ty = threadIdx.x >> 5;
    #pragma unroll
    for (int i = ty; i < 32; i += 8)
        t[i][tx] = in[(size_t)(kb+i)*HID + nb + tx];
    __syncthreads();
    #pragma unroll
    for (int i = ty; i < 32; i += 8)
        out[(size_t)(nb+i)*HID + kb + tx] = __float2half_rn(t[tx][i]);
}
// weT fp16, col-permuted: fragment (j=2t+p, q, pair) -> col = half*128 + hh*64 + t*16 + q*4 + p*2 + pair
__global__ void k_weT(const float* __restrict__ we){
    int t = blockIdx.x*blockDim.x + threadIdx.x;
    if (t >= HID*EDIM) return;
    int n_f = t >> 5, k = t & 31;
    int half = n_f >> 7, rem = n_f & 127;
    int hh  = rem >> 6;
    int jm  = (rem >> 3) & 7;
    int low = rem & 7, qq = low >> 1, pair = low & 1;
    int tt = jm >> 1, p = jm & 1;
    int a = half*128 + hh*64 + tt*16 + qq*4 + p*2 + pair;
    g_weT[t] = __float2half_rn(we[(size_t)k*HID + a]);
}

// ---------------- FP16 m16n8k16 GEMM, optional fused LN on A -----------------
#define HPAD 40
__global__ __launch_bounds__(256) void tgemm(
    const float* __restrict__ A, const __half* __restrict__ Bt,
    const float* __restrict__ bias, float* __restrict__ C,
    __half* __restrict__ Ch,
    const float* __restrict__ lnw, const float* __restrict__ lnb,
    const double* __restrict__ red,
    int M, int K, int Nn, int act)
{
    __shared__ __half As[2][128*HPAD];
    __shared__ __half Bs[2][128*HPAD];
    __shared__ float sTab[384], bTab[384];
    const int tid = threadIdx.x, lane = tid & 31, wid = tid >> 5;
    const int wm = (wid & 1)*64, wn = (wid >> 1)*32;
    const int cRow = blockIdx.y*128, cCol = blockIdx.x*128;
    const int r0 = tid >> 1, seg = (tid & 1)*16;
    const bool doNorm = (lnw != nullptr);

    if (doNorm) {
        double mu, rs;
        ln_params(red, &mu, &rs);
        for (int k = tid; k < K; k += 256) {
            float sc = (float)rs * lnw[k];
            sTab[k] = sc;
            bTab[k] = lnb[k] - (float)mu * sc;
        }
    }
    __syncthreads();

    const int aoff = (((lane & 15))*HPAD + (lane >> 4)*8)*2;
    const int boff = ((((lane & 7) + ((lane >> 4) << 3)))*HPAD + ((lane >> 3) & 1)*8)*2;

    float acc[4][4][4];
    #pragma unroll
    for (int i = 0; i < 4; i++)
        #pragma unroll
        for (int j = 0; j < 4; j++)
            #pragma unroll
            for (int v = 0; v < 4; v++) acc[i][j][v] = 0.f;

    float4 aF[4];
    uint4  bF[2];
#define LDG_TILE(kt) { \
    int gr = cRow + r0; \
    if (gr < M) { \
        const float* p = A + (size_t)gr*K + (kt) + seg; \
        aF[0] = *(const float4*)(p); aF[1] = *(const float4*)(p+4); \
        aF[2] = *(const float4*)(p+8); aF[3] = *(const float4*)(p+12); \
    } else { \
        aF[0]=aF[1]=aF[2]=aF[3]=make_float4(0,0,0,0); \
    } \
    if (doNorm) { \
        _Pragma("unroll") \
        for (int u = 0; u < 4; u++) { \
            float4 sc = *(const float4*)(sTab + (kt) + seg + u*4); \
            float4 bs = *(const float4*)(bTab + (kt) + seg + u*4); \
            aF[u].x = aF[u].x*sc.x + bs.x; aF[u].y = aF[u].y*sc.y + bs.y; \
            aF[u].z = aF[u].z*sc.z + bs.z; aF[u].w = aF[u].w*sc.w + bs.w; \
        } \
    } \
    const uint4* pb = (const uint4*)(Bt + (size_t)(cCol + r0)*K + (kt) + seg); \
    bF[0] = pb[0]; bF[1] = pb[1]; }
#define STS_TILE(b) { \
    uint4 h0, h1; \
    ((__half2*)&h0)[0] = __floats2half2_rn(aF[0].x, aF[0].y); \
    ((__half2*)&h0)[1] = __floats2half2_rn(aF[0].z, aF[0].w); \
    ((__half2*)&h0)[2] = __floats2half2_rn(aF[1].x, aF[1].y); \
    ((__half2*)&h0)[3] = __floats2half2_rn(aF[1].z, aF[1].w); \
    ((__half2*)&h1)[0] = __floats2half2_rn(aF[2].x, aF[2].y); \
    ((__half2*)&h1)[1] = __floats2half2_rn(aF[2].z, aF[2].w); \
    ((__half2*)&h1)[2] = __floats2half2_rn(aF[3].x, aF[3].y); \
    ((__half2*)&h1)[3] = __floats2half2_rn(aF[3].z, aF[3].w); \
    uint4* pa = (uint4*)(&As[b][r0*HPAD + seg]); \
    pa[0] = h0; pa[1] = h1; \
    uint4* pb2 = (uint4*)(&Bs[b][r0*HPAD + seg]); \
    pb2[0] = bF[0]; pb2[1] = bF[1]; }
#define COMPUTE(b) { \
    uint32_t ab = sptr(&As[b][0]) + wm*HPAD*2 + aoff; \
    uint32_t bb = sptr(&Bs[b][0]) + wn*HPAD*2 + boff; \
    _Pragma("unroll") \
    for (int ks = 0; ks < 2; ks++) { \
        uint4 af0, af1, af2, af3, bf0, bf1; \
        LDSM4(af0, ab + ks*32); \
        LDSM4(af1, ab + 16*HPAD*2 + ks*32); \
        LDSM4(af2, ab + 32*HPAD*2 + ks*32); \
        LDSM4(af3, ab + 48*HPAD*2 + ks*32); \
        LDSM4(bf0, bb + ks*32); \
        LDSM4(bf1, bb + 16*HPAD*2 + ks*32); \
        mmaH(acc[0][0], af0, bf0.x, bf0.y); mmaH(acc[0][1], af0, bf0.z, bf0.w); \
        mmaH(acc[0][2], af0, bf1.x, bf1.y); mmaH(acc[0][3], af0, bf1.z, bf1.w); \
        mmaH(acc[1][0], af1, bf0.x, bf0.y); mmaH(acc[1][1], af1, bf0.z, bf0.w); \
        mmaH(acc[1][2], af1, bf1.x, bf1.y); mmaH(acc[1][3], af1, bf1.z, bf1.w); \
        mmaH(acc[2][0], af2, bf0.x, bf0.y); mmaH(acc[2][1], af2, bf0.z, bf0.w); \
        mmaH(acc[2][2], af2, bf1.x, bf1.y); mmaH(acc[2][3], af2, bf1.z, bf1.w); \
        mmaH(acc[3][0], af3, bf0.x, bf0.y); mmaH(acc[3][1], af3, bf0.z, bf0.w); \
        mmaH(acc[3][2], af3, bf1.x, bf1.y); mmaH(acc[3][3], af3, bf1.z, bf1.w); \
    } }

    LDG_TILE(0);
    STS_TILE(0);
    __syncthreads();
    int buf = 0;
    for (int kt = 32; kt < K; kt += 32) {
        LDG_TILE(kt);
        COMPUTE(buf);
        STS_TILE(buf ^ 1);
        __syncthreads();
        buf ^= 1;
    }
    COMPUTE(buf);

    const int g = lane >> 2, q = lane & 3;
    #pragma unroll
    for (int mf = 0; mf < 4; mf++) {
        int rA = cRow + wm + mf*16 + g;
        #pragma unroll
        for (int nf = 0; nf < 4; nf++) {
            int col = cCol + wn + nf*8 + 2*q;
            float bx = 0.f, by = 0.f;
            if (bias) { float2 bb = *(const float2*)(bias + col); bx = bb.x; by = bb.y; }
            float v0 = acc[mf][nf][0] + bx, v1 = acc[mf][nf][1] + by;
            float v2 = acc[mf][nf][2] + bx, v3 = acc[mf][nf][3] + by;
            if (act == 1) {
                v0 = fmaxf(v0,0.f); v1 = fmaxf(v1,0.f);
                v2 = fmaxf(v2,0.f); v3 = fmaxf(v3,0.f);
            }
            if (Ch) {
                if (rA < M)
                    *(__half2*)(Ch + (size_t)rA*Nn + col) = __floats2half2_rn(v0, v1);
                if (rA+8 < M)
                    *(__half2*)(Ch + (size_t)(rA+8)*Nn + col) = __floats2half2_rn(v2, v3);
            } else {
                if (rA < M)     *(float2*)(C + (size_t)rA*Nn + col)     = make_float2(v0,v1);
                if (rA+8 < M)   *(float2*)(C + (size_t)(rA+8)*Nn + col) = make_float2(v2,v3);
            }
        }
    }
#undef LDG_TILE
#undef STS_TILE
#undef COMPUTE
}

// ---------------- fused ep-GEMM + logits (fp16 mma); stores exp --------------
#define EPH 40   /* halves per row (32 + pad) */
__global__ __launch_bounds__(256) void k_eplogits(const float* __restrict__ attL)
{
    __shared__ __half As[128*EPH];    // 10 KB
    __shared__ __half Bs[256*EPH];    // 20.5 KB
    __shared__ int s_src[128], s_dst[128];
    const int tid = threadIdx.x, lane = tid & 31, wid = tid >> 5;
    const int q = lane & 3, g = lane >> 2;
    const int e0 = blockIdx.x * 128;

    for (int i = tid; i < 128; i += 256) {
        int pos = e0 + i, s = 0, d = 0;
        if (pos < ETOT) { s = g_csr_s[pos]; d = g_csr_d[pos]; }
        s_src[i] = s; s_dst[i] = d;
    }
    #pragma unroll
    for (int i = 0; i < 2; i++) {      // As: 512 uint4, direct fp16 copy
        int f = tid + i*256;
        int row = f >> 2, q4 = f & 3;
        int pos = e0 + row;
        uint4 raw = make_uint4(0,0,0,0);
        if (pos < ETOT)
            raw = __ldcs((const uint4*)(g_each + (size_t)pos*EDIM + q4*8));
        *(uint4*)(&As[row*EPH + q4*8]) = raw;
    }
    #pragma unroll
    for (int i = 0; i < 4; i++) {      // Bs: 1024 uint4
        int f = tid + i*256;
        int row = f >> 2, q4 = f & 3;
        *(uint4*)(&Bs[row*EPH + q4*8]) =
            *(const uint4*)(g_weT + (size_t)row*EDIM + q4*8);
    }
    __syncthreads();

    const int aoff = (((lane & 15))*EPH + (lane >> 4)*8)*2;
    const int boff = ((((lane & 7) + ((lane >> 4) << 3)))*EPH + ((lane >> 3) & 1)*8)*2;
    const int r0l = wid*16 + g, r1l = r0l + 8;
    const int s0 = s_src[r0l], d0 = s_dst[r0l];
    const int s1 = s_src[r1l], d1 = s_dst[r1l];
    const uint32_t ab = sptr(&As[0]) + wid*16*EPH*2 + aoff;
    const uint32_t bb = sptr(&Bs[0]) + boff;

    #pragma unroll
    for (int half = 0; half < 2; half++) {
        float acc[16][4];
        #pragma unroll
        for (int j = 0; j < 16; j++)
            #pragma unroll
            for (int v = 0; v < 4; v++) acc[j][v] = 0.f;
        uint32_t bbh = bb + half*(128*EPH*2);
        #pragma unroll
        for (int ks = 0; ks < 2; ks++) {
            uint4 a;
            LDSM4(a, ab + ks*32);
            #pragma unroll
            for (int nt = 0; nt < 8; nt++) {
                uint4 b;
                LDSM4(b, bbh + nt*16*EPH*2 + ks*32);
                mmaH(acc[nt*2+0], a, b.x, b.y);
                mmaH(acc[nt*2+1], a, b.z, b.w);
            }
        }
        float p0h0 = 0.f, p0h1 = 0.f, p1h0 = 0.f, p1h1 = 0.f;
        #pragma unroll
        for (int hh = 0; hh < 2; hh++) {
            #pragma unroll
            for (int t = 0; t < 4; t++) {
                int cb = half*128 + hh*64 + t*16 + q*4;
                float4 at = *(const float4*)(attL + cb);
                uint2 ra0 = *(const uint2*)(g_xlrh + (size_t)s0*512 + cb);
                uint2 rb0 = *(const uint2*)(g_xlrh + (size_t)d0*512 + 256 + cb);
                uint2 ra1 = *(const uint2*)(g_xlrh + (size_t)s1*512 + cb);
                uint2 rb1 = *(const uint2*)(g_xlrh + (size_t)d1*512 + 256 + cb);
                float2 a0l = __half22float2(*(__half2*)&ra0.x);
                float2 a0h = __half22float2(*(__half2*)&ra0.y);
                float2 b0l = __half22float2(*(__half2*)&rb0.x);
                float2 b0h = __half22float2(*(__half2*)&rb0.y);
                float2 a1l = __half22float2(*(__half2*)&ra1.x);
                float2 a1h = __half22float2(*(__half2*)&ra1.y);
                float2 b1l = __half22float2(*(__half2*)&rb1.x);
                float2 b1h = __half22float2(*(__half2*)&rb1.y);
                int ja = hh*8 + 2*t;
                float c0 = lrelu(acc[ja][0]   + a0l.x + b0l.x)*at.x
                         + lrelu(acc[ja][1]   + a0l.y + b0l.y)*at.y
                         + lrelu(acc[ja+1][0] + a0h.x + b0h.x)*at.z
                         + lrelu(acc[ja+1][1] + a0h.y + b0h.y)*at.w;
                float c1 = lrelu(acc[ja][2]   + a1l.x + b1l.x)*at.x
                         + lrelu(acc[ja][3]   + a1l.y + b1l.y)*at.y
                         + lrelu(acc[ja+1][2] + a1h.x + b1h.x)*at.z
                         + lrelu(acc[ja+1][3] + a1h.y + b1h.y)*at.w;
                if (hh == 0) { p0h0 += c0; p1h0 += c1; }
                else         { p0h1 += c0; p1h1 += c1; }
            }
        }
        #pragma unroll
        for (int off = 1; off <= 2; off <<= 1) {
            p0h0 += __shfl_xor_sync(0xffffffffu, p0h0, off);
            p0h1 += __shfl_xor_sync(0xffffffffu, p0h1, off);
            p1h0 += __shfl_xor_sync(0xffffffffu, p1h0, off);
            p1h1 += __shfl_xor_sync(0xffffffffu, p1h1, off);
        }
        if (q == 0) {
            if (e0 + r0l < ETOT) {
                g_logits[(size_t)(e0 + r0l)*HEADS + half*2 + 0] = __expf(p0h0);
                g_logits[(size_t)(e0 + r0l)*HEADS + half*2 + 1] = __expf(p0h1);
            }
            if (e0 + r1l < ETOT) {
                g_logits[(size_t)(e0 + r1l)*HEADS + half*2 + 0] = __expf(p1h0);
                g_logits[(size_t)(e0 + r1l)*HEADS + half*2 + 1] = __expf(p1h1);
            }
        }
    }
}

// ---------------- node aggregation: single pass ------------------------------
__global__ __launch_bounds__(256) void k_nodeagg(
    const float* __restrict__ bconv,
    const float* __restrict__ lnwP, const float* __restrict__ lnbP,
    const double* __restrict__ redP, double* __restrict__ redO)
{
    const int n    = (blockIdx.x*256 + threadIdx.x) >> 5;
    const int lane = threadIdx.x & 31;
    const int p0 = g_csr_ptr[n], p1 = g_csr_ptr[n+1];
    const int head = lane >> 3;
    float acc[8];
    #pragma unroll
    for (int j = 0; j < 8; j++) acc[j] = 0.f;
    float dsum = 0.f;
    int   s_nx   = g_csr_s[p0];
    float4 ex_nx = *(const float4*)(g_logits + (size_t)p0*HEADS);
    uint4  raw_nx = *(const uint4*)(g_xlrh + (size_t)s_nx*512 + lane*8);
    for (int idx = p0; idx < p1; idx++) {
        float4 ex = ex_nx;
        uint4 raw = raw_nx;
        if (idx + 1 < p1) {
            int s2 = g_csr_s[idx+1];
            ex_nx  = *(const float4*)(g_logits + (size_t)(idx+1)*HEADS);
            raw_nx = *(const uint4*)(g_xlrh + (size_t)s2*512 + lane*8);
        }
        float w = sel4(ex, head);
        dsum += w;
        float2 f0 = __half22float2(*(__half2*)&raw.x);
        float2 f1 = __half22float2(*(__half2*)&raw.y);
        float2 f2 = __half22float2(*(__half2*)&raw.z);
        float2 f3 = __half22float2(*(__half2*)&raw.w);
        acc[0] += w*f0.x; acc[1] += w*f0.y; acc[2] += w*f1.x; acc[3] += w*f1.y;
        acc[4] += w*f2.x; acc[5] += w*f2.y; acc[6] += w*f3.x; acc[7] += w*f3.y;
    }
    const float ih = 1.f / (dsum + 1e-16f);
    float* ph = g_h + (size_t)n*HID + lane*8;
    float4 h0 = __ldcs((const float4*)ph);
    float4 h1 = __ldcs((const float4*)(ph+4));
    float4 b0 = *(const float4*)(bconv + lane*8);
    float4 b1 = *(const float4*)(bconv + lane*8 + 4);
    float hv[8] = {h0.x,h0.y,h0.z,h0.w,h1.x,h1.y,h1.z,h1.w};
    float bv[8] = {b0.x,b0.y,b0.z,b0.w,b1.x,b1.y,b1.z,b1.w};
    if (lnwP) {
        double mu, rs;
        ln_params(redP, &mu, &rs);
        float4 w0 = *(const float4*)(lnwP + lane*8);
        float4 w1 = *(const float4*)(lnwP + lane*8 + 4);
        float4 l0 = *(const float4*)(lnbP + lane*8);
        float4 l1 = *(const float4*)(lnbP + lane*8 + 4);
        float wv[8] = {w0.x,w0.y,w0.z,w0.w,w1.x,w1.y,w1.z,w1.w};
        float lv[8] = {l0.x,l0.y,l0.z,l0.w,l1.x,l1.y,l1.z,l1.w};
        #pragma unroll
        for (int j = 0; j < 8; j++) {
            float sc = (float)rs * wv[j];
            hv[j] = hv[j]*sc + (lv[j] - (float)mu*sc);
        }
    }
    float s_ = 0.f, q_ = 0.f;
    float out8[8];
    #pragma unroll
    for (int j = 0; j < 8; j++) {
        float v  = acc[j]*ih + bv[j];
        float el = v > 0.f ? v : (__expf(v) - 1.f);
        float t  = hv[j] + el;
        out8[j] = t; s_ += t; q_ += t*t;
    }
    __stcs((float4*)ph,     make_float4(out8[0],out8[1],out8[2],out8[3]));
    __stcs((float4*)(ph+4), make_float4(out8[4],out8[5],out8[6],out8[7]));
    #pragma unroll
    for (int off = 16; off; off >>= 1) {
        s_ += __shfl_down_sync(0xffffffffu, s_, off);
        q_ += __shfl_down_sync(0xffffffffu, q_, off);
    }
    __shared__ float ss[8], sq[8];
    int w = threadIdx.x >> 5;
    if (lane == 0) { ss[w] = s_; sq[w] = q_; }
    __syncthreads();
    if (threadIdx.x == 0) {
        float S = 0.f, Q = 0.f;
        #pragma unroll
        for (int i = 0; i < 8; i++) { S += ss[i]; Q += sq[i]; }
        atomicAdd(&redO[0], (double)S);
        atomicAdd(&redO[1], (double)Q);
    }
}

// ---------------- launcher ---------------------------------------------------
extern "C" void kernel_launch(void* const* d_in, const int* in_sizes, int n_in,
                              void* d_out, int out_size)
{
    const float* x     = (const float*)d_in[0];
    const int*   ei    = (const int*)  d_in[1];
    const float* ea    = (const float*)d_in[2];
    const float* w_in  = (const float*)d_in[3];
    const float* b_in  = (const float*)d_in[4];
    const float* wl    = (const float*)d_in[5];
    const float* wr    = (const float*)d_in[6];
    const float* we    = (const float*)d_in[7];
    const float* att   = (const float*)d_in[8];
    const float* bconv = (const float*)d_in[9];
    const float* lnw   = (const float*)d_in[10];
    const float* lnb   = (const float*)d_in[11];
    const float* wout  = (const float*)d_in[12];
    const float* bout  = (const float*)d_in[13];
    float* out = (float*)d_out;
    const int* srcA = ei;
    const int* dstA = ei + NE;

    float *p_h;
    __half *p_xlrh, *p_winT, *p_wcatT, *p_woutT;
    int* p_degi;
    double* p_red;
    cudaGetSymbolAddress((void**)&p_h,     g_h);
    cudaGetSymbolAddress((void**)&p_xlrh,  g_xlrh);
    cudaGetSymbolAddress((void**)&p_degi,  g_degi);
    cudaGetSymbolAddress((void**)&p_winT,  g_winT);
    cudaGetSymbolAddress((void**)&p_wcatT, g_wcatT);
    cudaGetSymbolAddress((void**)&p_woutT, g_woutT);
    cudaGetSymbolAddress((void**)&p_red,   g_redL);
    double* redL0 = p_red;
    double* redL1 = p_red + 2;

    dim3 gIn (HID/128, (N_NODES + 127)/128);
    dim3 gXlr(512/128, (N_NODES + 127)/128);

    k_transpose<<<dim3(HID/32, DIN/32), 256>>>(w_in, p_winT, DIN, HID);
    tgemm<<<gIn, 256>>>(x, p_winT, b_in, p_h, nullptr,
                        nullptr, nullptr, nullptr, N_NODES, DIN, HID, 1);
    k_transcat<<<dim3(8, 8, 2), 256>>>(wl, wr);
    tgemm<<<gXlr, 256>>>(p_h, p_wcatT, nullptr, nullptr, p_xlrh,
                         nullptr, nullptr, nullptr, N_NODES, HID, 512, 0);

    k_zero_i<<<(N_NODES + 511)/512, 512>>>(p_degi, N_NODES);
    k_degc<<<(NE + 255)/256, 256>>>(dstA);
    k_scan<<<1, 1024>>>();
    k_scatter<<<(ETOT + 255)/256, 256>>>(srcA, dstA);
    k_eafuse<<<N_NODES/8, 256>>>(ea);
    k_transpose<<<dim3(HID/32, HID/32), 256>>>(wout, p_woutT, HID, HID);

    // ---- layer 0 ----
    k_weT<<<(HID*EDIM + 255)/256, 256>>>(we);
    k_eplogits<<<(ETOT + 127)/128, 256>>>(att);
    k_nodeagg<<<N_NODES/8, 256>>>(bconv, nullptr, nullptr, nullptr, redL0);

    // ---- layer 1 ----
    k_transcat<<<dim3(8, 8, 2), 256>>>(wl + (size_t)HID*HID, wr + (size_t)HID*HID);
    tgemm<<<gXlr, 256>>>(p_h, p_wcatT, nullptr, nullptr, p_xlrh,
                         lnw, lnb, redL0, N_NODES, HID, 512, 0);
    k_weT<<<(HID*EDIM + 255)/256, 256>>>(we + (size_t)EDIM*HID);
    k_eplogits<<<(ETOT + 127)/128, 256>>>(att + (size_t)HEADS*CDIM);
    k_nodeagg<<<N_NODES/8, 256>>>(bconv + HID, lnw, lnb, redL0, redL1);

    // ---- output GEMM applies layer-1 LN ----
    tgemm<<<gIn, 256>>>(p_h, p_woutT, bout, out, nullptr,
                        lnw + HID, lnb + HID, redL1, N_NODES, HID, HID, 0);
}